// round 6
// baseline (speedup 1.0000x reference)
#include <cuda_runtime.h>
#include <cstdint>

#define DCH 128
#define TMR 64
#define ROWB 288               // bytes per smem plane row (256 data + 32 pad)

#define OFF_A   0
#define OFF_B   (64 * ROWB)                 // 18432
#define OFF_SA  (OFF_B + 128 * ROWB)        // 55296 : float sA[64]
#define OFF_SB  (OFF_SA + 256)              // 55552 : float sB[128]
#define OFF_PS  (OFF_SB + 512)              // 56064 : ps[4][64], pq[4][64]
#define OFF_PM  (OFF_PS + 2048)             // 58112 : pm[4][64]
#define SMEM_SZ (OFF_PM + 1024 + 64)

#define SLAB_B  (128 * 256 + 512)           // int8 digit planes + float sb[128]

// ---------------- scratch (alloc-free) ----------------
__device__ float g_qc[4000 * 128];
__device__ float g_nc[20000 * 128];
__device__ float g_acc[4000 * 128];
__device__ float g_agts[4000 * 128];
__device__ __align__(16) unsigned char g_wp[2 * 8 * SLAB_B];

// slabs: 0=Wq 1=Wc1a 2=Wc1b 3=Wc1c 4=Wc2 5=Wa 6=Wl 7=Wd2

struct P {
  const float* agts; const float* nodes;
  const float* actor_ctrs; const float* node_ctrs;
  const int* hi; const int* wi;
  const unsigned char* wp;
  const float* Wd1; const float* bd1;
  const float *gnq_w, *gnq_b, *gnd2_w, *gnd2_b, *gnc1_w, *gnc1_b,
              *gnn_w, *gnn_b, *gnl_w, *gnl_b;
  float *qc, *nc, *acc, *out;
  int M, N, E, mb, nb;
};

__device__ __forceinline__ uint32_t smem_u32(const void* p) {
  uint32_t a;
  asm("{ .reg .u64 t; cvta.to.shared.u64 t, %1; cvt.u32.u64 %0, t; }" : "=r"(a) : "l"(p));
  return a;
}
#define LDS64(x, y, addr) \
  asm volatile("ld.shared.v2.u32 {%0,%1}, [%2];" : "=r"(x), "=r"(y) : "r"(addr))
#define STS16(addr, v) \
  asm volatile("st.shared.u16 [%0], %1;" :: "r"(addr), "h"((unsigned short)(v)))

__device__ __forceinline__ void mma_s8(int c[4], uint32_t a0, uint32_t a1,
                                       uint32_t a2, uint32_t a3,
                                       uint32_t b0, uint32_t b1) {
  asm volatile(
    "mma.sync.aligned.m16n8k32.row.col.s32.s8.s8.s32 "
    "{%0,%1,%2,%3}, {%4,%5,%6,%7}, {%8,%9}, {%0,%1,%2,%3};"
    : "+r"(c[0]), "+r"(c[1]), "+r"(c[2]), "+r"(c[3])
    : "r"(a0), "r"(a1), "r"(a2), "r"(a3), "r"(b0), "r"(b1));
}

__device__ __forceinline__ void quant2(float x, float inv, int& d1, int& d2) {
  float xs = fminf(fmaxf(x * inv, -127.f), 127.f);
  d1 = __float2int_rn(xs);
  d2 = __float2int_rn((xs - (float)d1) * 127.f);
}
__device__ __forceinline__ uint32_t packb(int b0, int b1, int b2, int b3) {
  return (b0 & 0xff) | ((b1 & 0xff) << 8) | ((b2 & 0xff) << 16) | ((b3 & 0xff) << 24);
}

// quantize a full row-chunk: thread owns row r, kstep q (32 values)
__device__ __forceinline__ void quant_store_A(char* smem, const float v[32], int r, int q) {
  float m = 0.f;
#pragma unroll
  for (int i = 0; i < 32; i++) m = fmaxf(m, fabsf(v[i]));
  m = fmaxf(m, __shfl_xor_sync(0xffffffffu, m, 1));
  m = fmaxf(m, __shfl_xor_sync(0xffffffffu, m, 2));
  float inv = m > 0.f ? 127.f / m : 0.f;
  int d1[32], d2[32];
#pragma unroll
  for (int i = 0; i < 32; i++) quant2(v[i], inv, d1[i], d2[i]);
  char* rowp = smem + OFF_A + r * ROWB + q * 32;
#pragma unroll
  for (int j = 0; j < 4; j++) {
    uint2 u1 = make_uint2(packb(d1[4 * j], d1[4 * j + 1], d1[4 * j + 2], d1[4 * j + 3]),
                          packb(d1[16 + 4 * j], d1[17 + 4 * j], d1[18 + 4 * j], d1[19 + 4 * j]));
    *(uint2*)(rowp + j * 8) = u1;
    uint2 u2 = make_uint2(packb(d2[4 * j], d2[4 * j + 1], d2[4 * j + 2], d2[4 * j + 3]),
                          packb(d2[16 + 4 * j], d2[17 + 4 * j], d2[18 + 4 * j], d2[19 + 4 * j]));
    *(uint2*)(rowp + 128 + j * 8) = u2;
  }
  if (q == 0) ((float*)(smem + OFF_SA))[r] = m;
}

__device__ __forceinline__ void copy_B(char* smem, const unsigned char* wps) {
  const uint4* src = (const uint4*)wps;
  for (int i = threadIdx.x; i < 2048; i += 256) {
    int row = i >> 4, u = i & 15;
    *(uint4*)(smem + OFF_B + row * ROWB + u * 16) = src[i];
  }
  if (threadIdx.x < 128)
    ((float*)(smem + OFF_SB))[threadIdx.x] = ((const float*)(wps + 32768))[threadIdx.x];
}

__device__ __forceinline__ void mainloop_i8(const char* smem, int accM[2][4][4],
                                            int accC[2][4][4],
                                            int rowb, int cwb, int g, int tg) {
  const uint32_t Ab = smem_u32(smem) + OFF_A;
  const uint32_t Bb = smem_u32(smem) + OFF_B;
#pragma unroll
  for (int ms = 0; ms < 2; ms++)
#pragma unroll
    for (int ns = 0; ns < 4; ns++)
#pragma unroll
      for (int q = 0; q < 4; q++) { accM[ms][ns][q] = 0; accC[ms][ns][q] = 0; }
#pragma unroll
  for (int ks = 0; ks < 8; ks++) {
    uint32_t a[2][4];
#pragma unroll
    for (int ms = 0; ms < 2; ms++) {
      const int r0 = rowb + ms * 16 + g;
      LDS64(a[ms][0], a[ms][2], Ab + r0 * ROWB + ks * 32 + tg * 8);
      LDS64(a[ms][1], a[ms][3], Ab + (r0 + 8) * ROWB + ks * 32 + tg * 8);
    }
#pragma unroll
    for (int ns = 0; ns < 4; ns++) {
      const int n = cwb + ns * 8 + g;
      uint32_t b0, b1;
      LDS64(b0, b1, Bb + n * ROWB + ks * 32 + tg * 8);
#pragma unroll
      for (int ms = 0; ms < 2; ms++)
        mma_s8(accC[ms][ns], a[ms][0], a[ms][1], a[ms][2], a[ms][3], b0, b1);
      if (ks < 4) {
        uint32_t c0, c1;
        LDS64(c0, c1, Bb + n * ROWB + (ks + 4) * 32 + tg * 8);
#pragma unroll
        for (int ms = 0; ms < 2; ms++)
          mma_s8(accM[ms][ns], a[ms][0], a[ms][1], a[ms][2], a[ms][3], c0, c1);
      }
    }
  }
}

__device__ __forceinline__ void decode(const char* smem, const int accM[2][4][4],
                                       const int accC[2][4][4], float f[2][4][4],
                                       int rowb, int cwb, int g, int tg) {
  const float* sA = (const float*)(smem + OFF_SA);
  const float* sB = (const float*)(smem + OFF_SB);
  const int c0 = cwb + tg * 2;
  float sb[4][2];
#pragma unroll
  for (int ns = 0; ns < 4; ns++) {
    sb[ns][0] = sB[c0 + ns * 8];
    sb[ns][1] = sB[c0 + ns * 8 + 1];
  }
#pragma unroll
  for (int ms = 0; ms < 2; ms++)
#pragma unroll
    for (int h = 0; h < 2; h++) {
      const float ka = sA[rowb + ms * 16 + h * 8 + g] * (1.f / 16129.f);
#pragma unroll
      for (int ns = 0; ns < 4; ns++)
#pragma unroll
        for (int j = 0; j < 2; j++) {
          float t = fmaf((float)accC[ms][ns][2 * h + j], (1.f / 127.f),
                         (float)accM[ms][ns][2 * h + j]);
          f[ms][ns][2 * h + j] = t * (ka * sb[ns][j]);
        }
    }
}

// GroupNorm (1 group, 128 ch) — one internal syncthreads
__device__ __forceinline__ void gn_ep(float f[2][4][4], char* smem,
                                      const float* gnw, const float* gnb,
                                      int rowb, int cwb, int nw, int g, int tg,
                                      bool dorelu) {
  float* ps = (float*)(smem + OFF_PS);
  float* pq = ps + 256;
#pragma unroll
  for (int ms = 0; ms < 2; ms++)
#pragma unroll
    for (int h = 0; h < 2; h++) {
      float s = 0.f, q = 0.f;
#pragma unroll
      for (int ns = 0; ns < 4; ns++)
#pragma unroll
        for (int j = 0; j < 2; j++) {
          float v = f[ms][ns][2 * h + j];
          s += v;
          q = fmaf(v, v, q);
        }
      s += __shfl_xor_sync(0xffffffffu, s, 1);
      q += __shfl_xor_sync(0xffffffffu, q, 1);
      s += __shfl_xor_sync(0xffffffffu, s, 2);
      q += __shfl_xor_sync(0xffffffffu, q, 2);
      const int r = rowb + ms * 16 + h * 8 + g;
      if (tg == 0) { ps[nw * 64 + r] = s; pq[nw * 64 + r] = q; }
    }
  __syncthreads();
  const int c0 = cwb + tg * 2;
  float2 gwv[4], gbv[4];
#pragma unroll
  for (int ns = 0; ns < 4; ns++) {
    gwv[ns] = *(const float2*)(gnw + c0 + ns * 8);
    gbv[ns] = *(const float2*)(gnb + c0 + ns * 8);
  }
#pragma unroll
  for (int ms = 0; ms < 2; ms++)
#pragma unroll
    for (int h = 0; h < 2; h++) {
      const int r = rowb + ms * 16 + h * 8 + g;
      float s = ps[r] + ps[64 + r] + ps[128 + r] + ps[192 + r];
      float q = pq[r] + pq[64 + r] + pq[128 + r] + pq[192 + r];
      float m = s * (1.f / DCH);
      float var = q * (1.f / DCH) - m * m;
      float inv = rsqrtf(var + 1e-5f);
#pragma unroll
      for (int ns = 0; ns < 4; ns++) {
        float a0 = fmaf((f[ms][ns][2 * h]     - m) * inv, gwv[ns].x, gbv[ns].x);
        float a1 = fmaf((f[ms][ns][2 * h + 1] - m) * inv, gwv[ns].y, gbv[ns].y);
        if (dorelu) { a0 = fmaxf(a0, 0.f); a1 = fmaxf(a1, 0.f); }
        f[ms][ns][2 * h]     = a0;
        f[ms][ns][2 * h + 1] = a1;
      }
    }
}

// requantize f into A plane + sA, and copy next B slab; 2 internal syncs
__device__ __forceinline__ void quant_repack(float f[2][4][4], char* smem,
                                             const unsigned char* next_wps,
                                             int rowb, int cwb, int nw, int g, int tg) {
  float* pm = (float*)(smem + OFF_PM);
#pragma unroll
  for (int ms = 0; ms < 2; ms++)
#pragma unroll
    for (int h = 0; h < 2; h++) {
      float m = 0.f;
#pragma unroll
      for (int ns = 0; ns < 4; ns++)
#pragma unroll
        for (int j = 0; j < 2; j++) m = fmaxf(m, fabsf(f[ms][ns][2 * h + j]));
      m = fmaxf(m, __shfl_xor_sync(0xffffffffu, m, 1));
      m = fmaxf(m, __shfl_xor_sync(0xffffffffu, m, 2));
      const int r = rowb + ms * 16 + h * 8 + g;
      if (tg == 0) pm[nw * 64 + r] = m;
    }
  copy_B(smem, next_wps);
  __syncthreads();
  const uint32_t Ab = smem_u32(smem) + OFF_A;
#pragma unroll
  for (int ms = 0; ms < 2; ms++)
#pragma unroll
    for (int h = 0; h < 2; h++) {
      const int r = rowb + ms * 16 + h * 8 + g;
      float s = fmaxf(fmaxf(pm[r], pm[64 + r]), fmaxf(pm[128 + r], pm[192 + r]));
      if (nw == 0 && tg == 0) ((float*)(smem + OFF_SA))[r] = s;
      float inv = s > 0.f ? 127.f / s : 0.f;
#pragma unroll
      for (int ns = 0; ns < 4; ns++) {
        const int c = cwb + ns * 8 + tg * 2;
        const int ks = c >> 5, kk = c & 31;
        const int boff = ks * 32 + ((kk & 15) >> 2) * 8 + (kk & 3) + ((kk >> 4) << 2);
        int d1a, d2a, d1b, d2b;
        quant2(f[ms][ns][2 * h],     inv, d1a, d2a);
        quant2(f[ms][ns][2 * h + 1], inv, d1b, d2b);
        STS16(Ab + r * ROWB + boff,       (d1a & 0xff) | ((d1b & 0xff) << 8));
        STS16(Ab + r * ROWB + 128 + boff, (d2a & 0xff) | ((d2b & 0xff) << 8));
      }
    }
  __syncthreads();
}

__device__ __forceinline__ void store_plain(const float f[2][4][4], float* Y, int row0,
                                            int rows, int rowb, int cwb, int g, int tg) {
  const int c0 = cwb + tg * 2;
#pragma unroll
  for (int ms = 0; ms < 2; ms++)
#pragma unroll
    for (int h = 0; h < 2; h++) {
      const int gr = row0 + rowb + ms * 16 + h * 8 + g;
      if (gr < rows) {
        float* dst = Y + (size_t)gr * DCH + c0;
#pragma unroll
        for (int ns = 0; ns < 4; ns++)
          *(float2*)(dst + ns * 8) =
              make_float2(f[ms][ns][2 * h], f[ms][ns][2 * h + 1]);
      }
    }
}

__device__ __forceinline__ void load_A_quant(char* smem, const float* X, int row0, int rows) {
  const int r = threadIdx.x >> 2, q = threadIdx.x & 3;
  const int gr = row0 + r;
  const float* px = X + (size_t)gr * DCH + q * 32;
  float v[32];
#pragma unroll
  for (int i = 0; i < 8; i++) {
    float4 t = (gr < rows) ? *(const float4*)(px + 4 * i) : make_float4(0.f, 0.f, 0.f, 0.f);
    v[4 * i] = t.x; v[4 * i + 1] = t.y; v[4 * i + 2] = t.z; v[4 * i + 3] = t.w;
  }
  quant_store_A(smem, v, r, q);
}

// ---------------- weight pack (int8 digit planes + row scales) ----------------
__global__ void wpack_kernel(const float* Wq, const float* Wc1, const float* Wc2,
                             const float* Wa, const float* Wl, const float* Wd2,
                             unsigned char* wp) {
  int L = blockIdx.x >> 3, s = blockIdx.x & 7;
  const float* src;
  int ldw = DCH, coff = 0;
  switch (s) {
    case 0: src = Wq  + (size_t)L * DCH * DCH; break;
    case 1: src = Wc1 + (size_t)L * DCH * 3 * DCH; ldw = 3 * DCH; coff = 0;       break;
    case 2: src = Wc1 + (size_t)L * DCH * 3 * DCH; ldw = 3 * DCH; coff = DCH;     break;
    case 3: src = Wc1 + (size_t)L * DCH * 3 * DCH; ldw = 3 * DCH; coff = 2 * DCH; break;
    case 4: src = Wc2 + (size_t)L * DCH * DCH; break;
    case 5: src = Wa  + (size_t)L * DCH * DCH; break;
    case 6: src = Wl  + (size_t)L * DCH * DCH; break;
    default: src = Wd2 + (size_t)L * DCH * DCH; break;
  }
  unsigned char* dst = wp + (size_t)(L * 8 + s) * SLAB_B;
  const int j = threadIdx.x;
  const float* wr = src + (size_t)j * ldw + coff;
  float m = 0.f;
#pragma unroll
  for (int i = 0; i < 32; i++) {
    float4 t = *(const float4*)(wr + 4 * i);
    m = fmaxf(m, fmaxf(fmaxf(fabsf(t.x), fabsf(t.y)), fmaxf(fabsf(t.z), fabsf(t.w))));
  }
  ((float*)(dst + 32768))[j] = m;
  float inv = m > 0.f ? 127.f / m : 0.f;
#pragma unroll
  for (int ks = 0; ks < 4; ks++) {
    float v[32];
#pragma unroll
    for (int i = 0; i < 8; i++) {
      float4 t = *(const float4*)(wr + ks * 32 + 4 * i);
      v[4 * i] = t.x; v[4 * i + 1] = t.y; v[4 * i + 2] = t.z; v[4 * i + 3] = t.w;
    }
    int d1[32], d2[32];
#pragma unroll
    for (int i = 0; i < 32; i++) quant2(v[i], inv, d1[i], d2[i]);
#pragma unroll
    for (int u = 0; u < 4; u++) {
      uint2 w1 = make_uint2(packb(d1[4 * u], d1[4 * u + 1], d1[4 * u + 2], d1[4 * u + 3]),
                            packb(d1[16 + 4 * u], d1[17 + 4 * u], d1[18 + 4 * u], d1[19 + 4 * u]));
      uint2 w2 = make_uint2(packb(d2[4 * u], d2[4 * u + 1], d2[4 * u + 2], d2[4 * u + 3]),
                            packb(d2[16 + 4 * u], d2[17 + 4 * u], d2[18 + 4 * u], d2[19 + 4 * u]));
      *(uint2*)(dst + (size_t)j * 256 + 128 + ks * 32 + u * 8) = w1;  // B1 (d1)
      *(uint2*)(dst + (size_t)j * 256 +       ks * 32 + u * 8) = w2;  // B2 (d2)
    }
  }
}

// ---------------- MN mega-kernel: {Wq->Wc1b | nodes->Wc1c | Wa} ----------------
__global__ void __launch_bounds__(256, 2) mn_kernel(P p) {
  extern __shared__ char smem[];
  const int tid = threadIdx.x, warp = tid >> 5, lane = tid & 31;
  const int mw = warp & 1, nw = warp >> 1;
  const int rowb = mw * 32, cwb = nw * 32, g = lane >> 2, tg = lane & 3;
  const int b = blockIdx.x;
  int accM[2][4][4], accC[2][4][4];
  float f[2][4][4];

  if (b < p.mb) {
    const int row0 = b * TMR;
    load_A_quant(smem, p.agts, row0, p.M);
    copy_B(smem, p.wp + 0 * SLAB_B);             // Wq
    __syncthreads();
    mainloop_i8(smem, accM, accC, rowb, cwb, g, tg);
    decode(smem, accM, accC, f, rowb, cwb, g, tg);
    gn_ep(f, smem, p.gnq_w, p.gnq_b, rowb, cwb, nw, g, tg, true);
    quant_repack(f, smem, p.wp + 2 * SLAB_B, rowb, cwb, nw, g, tg);   // Wc1b
    mainloop_i8(smem, accM, accC, rowb, cwb, g, tg);
    decode(smem, accM, accC, f, rowb, cwb, g, tg);
    store_plain(f, p.qc, row0, p.M, rowb, cwb, g, tg);
  } else if (b < p.mb + p.nb) {
    const int row0 = (b - p.mb) * TMR;
    load_A_quant(smem, p.nodes, row0, p.N);
    copy_B(smem, p.wp + 3 * SLAB_B);             // Wc1c
    __syncthreads();
    mainloop_i8(smem, accM, accC, rowb, cwb, g, tg);
    decode(smem, accM, accC, f, rowb, cwb, g, tg);
    store_plain(f, p.nc, row0, p.N, rowb, cwb, g, tg);
  } else {
    const int row0 = (b - p.mb - p.nb) * TMR;
    load_A_quant(smem, p.agts, row0, p.M);
    copy_B(smem, p.wp + 5 * SLAB_B);             // Wa
    __syncthreads();
    mainloop_i8(smem, accM, accC, rowb, cwb, g, tg);
    decode(smem, accM, accC, f, rowb, cwb, g, tg);
    store_plain(f, p.acc, row0, p.M, rowb, cwb, g, tg);
  }
}

// ---------------- E kernel: fused dist-MLP -> ctx-MLP -> scatter ----------------
__global__ void __launch_bounds__(256, 2) e_kernel(P p) {
  extern __shared__ char smem[];
  const int tid = threadIdx.x, warp = tid >> 5, lane = tid & 31;
  const int mw = warp & 1, nw = warp >> 1;
  const int rowb = mw * 32, cwb = nw * 32, g = lane >> 2, tg = lane & 3;
  const int row0 = blockIdx.x * TMR;
  int accM[2][4][4], accC[2][4][4];
  float f[2][4][4];

  // stage 1: A = relu(ctr_d @ Wd1^T + bd1), B = Wd2
  {
    const int r = tid >> 2, q = tid & 3;
    const int gr = row0 + r;
    float cx = 0.f, cy = 0.f;
    if (gr < p.E) {
      int h = p.hi[gr], w = p.wi[gr];
      cx = p.actor_ctrs[2 * h]     - p.node_ctrs[2 * w];
      cy = p.actor_ctrs[2 * h + 1] - p.node_ctrs[2 * w + 1];
    }
    float v[32];
#pragma unroll
    for (int i = 0; i < 32; i++) {
      const int k = q * 32 + i;
      v[i] = fmaxf(fmaf(cx, p.Wd1[2 * k], fmaf(cy, p.Wd1[2 * k + 1], p.bd1[k])), 0.f);
    }
    quant_store_A(smem, v, r, q);
  }
  copy_B(smem, p.wp + 7 * SLAB_B);               // Wd2
  __syncthreads();
  mainloop_i8(smem, accM, accC, rowb, cwb, g, tg);
  decode(smem, accM, accC, f, rowb, cwb, g, tg);
  gn_ep(f, smem, p.gnd2_w, p.gnd2_b, rowb, cwb, nw, g, tg, true);
  quant_repack(f, smem, p.wp + 1 * SLAB_B, rowb, cwb, nw, g, tg);     // Wc1a

  // stage 2: + qc[hi] + nc[wi], gn, relu
  mainloop_i8(smem, accM, accC, rowb, cwb, g, tg);
  decode(smem, accM, accC, f, rowb, cwb, g, tg);
  {
    const int c0 = cwb + tg * 2;
#pragma unroll
    for (int ms = 0; ms < 2; ms++)
#pragma unroll
      for (int h = 0; h < 2; h++) {
        const int gr = row0 + rowb + ms * 16 + h * 8 + g;
        if (gr < p.E) {
          const float* p1 = p.qc + (size_t)p.hi[gr] * DCH + c0;
          const float* p2 = p.nc + (size_t)p.wi[gr] * DCH + c0;
#pragma unroll
          for (int ns = 0; ns < 4; ns++) {
            float2 v1 = *(const float2*)(p1 + ns * 8);
            float2 v2 = *(const float2*)(p2 + ns * 8);
            f[ms][ns][2 * h]     += v1.x + v2.x;
            f[ms][ns][2 * h + 1] += v1.y + v2.y;
          }
        }
      }
  }
  gn_ep(f, smem, p.gnc1_w, p.gnc1_b, rowb, cwb, nw, g, tg, true);
  quant_repack(f, smem, p.wp + 4 * SLAB_B, rowb, cwb, nw, g, tg);     // Wc2

  // stage 3: acc[hi] += cf @ Wc2^T  (atomic scatter)
  mainloop_i8(smem, accM, accC, rowb, cwb, g, tg);
  decode(smem, accM, accC, f, rowb, cwb, g, tg);
  {
    const int c0 = cwb + tg * 2;
#pragma unroll
    for (int ms = 0; ms < 2; ms++)
#pragma unroll
      for (int h = 0; h < 2; h++) {
        const int gr = row0 + rowb + ms * 16 + h * 8 + g;
        if (gr < p.E) {
          float* dst = p.acc + (size_t)p.hi[gr] * DCH + c0;
#pragma unroll
          for (int ns = 0; ns < 4; ns++) {
            atomicAdd(dst + ns * 8,     f[ms][ns][2 * h]);
            atomicAdd(dst + ns * 8 + 1, f[ms][ns][2 * h + 1]);
          }
        }
      }
  }
}

// ---------------- F kernel: relu(gn(acc)) -> Wl -> gn + residual + relu ----------------
__global__ void __launch_bounds__(256, 2) f_kernel(P p) {
  extern __shared__ char smem[];
  const int tid = threadIdx.x, warp = tid >> 5, lane = tid & 31;
  const int mw = warp & 1, nw = warp >> 1;
  const int rowb = mw * 32, cwb = nw * 32, g = lane >> 2, tg = lane & 3;
  const int row0 = blockIdx.x * TMR;
  int accM[2][4][4], accC[2][4][4];
  float f[2][4][4];

  {
    const int r = tid >> 2, q = tid & 3;
    const int gr = row0 + r;
    float v[32];
    const float* px = p.acc + (size_t)gr * DCH + q * 32;
#pragma unroll
    for (int i = 0; i < 8; i++) {
      float4 t = (gr < p.M) ? *(const float4*)(px + 4 * i) : make_float4(0.f, 0.f, 0.f, 0.f);
      v[4 * i] = t.x; v[4 * i + 1] = t.y; v[4 * i + 2] = t.z; v[4 * i + 3] = t.w;
    }
    float s = 0.f, qq = 0.f;
#pragma unroll
    for (int i = 0; i < 32; i++) { s += v[i]; qq = fmaf(v[i], v[i], qq); }
    s  += __shfl_xor_sync(0xffffffffu, s, 1);
    qq += __shfl_xor_sync(0xffffffffu, qq, 1);
    s  += __shfl_xor_sync(0xffffffffu, s, 2);
    qq += __shfl_xor_sync(0xffffffffu, qq, 2);
    float m = s * (1.f / DCH);
    float var = qq * (1.f / DCH) - m * m;
    float inv = rsqrtf(var + 1e-5f);
#pragma unroll
    for (int i = 0; i < 32; i++) {
      const int c = q * 32 + i;
      v[i] = fmaxf(fmaf((v[i] - m) * inv, p.gnn_w[c], p.gnn_b[c]), 0.f);
    }
    quant_store_A(smem, v, r, q);
  }
  copy_B(smem, p.wp + 6 * SLAB_B);               // Wl
  __syncthreads();
  mainloop_i8(smem, accM, accC, rowb, cwb, g, tg);
  decode(smem, accM, accC, f, rowb, cwb, g, tg);
  gn_ep(f, smem, p.gnl_w, p.gnl_b, rowb, cwb, nw, g, tg, false);
  {
    const int c0 = cwb + tg * 2;
#pragma unroll
    for (int ms = 0; ms < 2; ms++)
#pragma unroll
      for (int h = 0; h < 2; h++) {
        const int gr = row0 + rowb + ms * 16 + h * 8 + g;
        if (gr < p.M) {
          const float* rp = p.agts + (size_t)gr * DCH + c0;
          float* dst = p.out + (size_t)gr * DCH + c0;
#pragma unroll
          for (int ns = 0; ns < 4; ns++) {
            float2 rv = *(const float2*)(rp + ns * 8);
            *(float2*)(dst + ns * 8) =
                make_float2(fmaxf(f[ms][ns][2 * h]     + rv.x, 0.f),
                            fmaxf(f[ms][ns][2 * h + 1] + rv.y, 0.f));
          }
        }
      }
  }
}

extern "C" void kernel_launch(void* const* d_in, const int* in_sizes, int n_in,
                              void* d_out, int out_size) {
  const float* actors     = (const float*)d_in[0];
  const float* nodes      = (const float*)d_in[1];
  const float* actor_ctrs = (const float*)d_in[2];
  const float* node_ctrs  = (const float*)d_in[3];
  const int*   hi         = (const int*)d_in[4];
  const int*   wi         = (const int*)d_in[5];
  const float* Wd1   = (const float*)d_in[6];
  const float* bd1   = (const float*)d_in[7];
  const float* Wd2   = (const float*)d_in[8];
  const float* gnd2w = (const float*)d_in[9];
  const float* gnd2b = (const float*)d_in[10];
  const float* Wq    = (const float*)d_in[11];
  const float* gnqw  = (const float*)d_in[12];
  const float* gnqb  = (const float*)d_in[13];
  const float* Wc1   = (const float*)d_in[14];
  const float* gnc1w = (const float*)d_in[15];
  const float* gnc1b = (const float*)d_in[16];
  const float* Wc2   = (const float*)d_in[17];
  const float* Wa    = (const float*)d_in[18];
  const float* gnnw  = (const float*)d_in[19];
  const float* gnnb  = (const float*)d_in[20];
  const float* Wl    = (const float*)d_in[21];
  const float* gnlw  = (const float*)d_in[22];
  const float* gnlb  = (const float*)d_in[23];

  const int M = in_sizes[0] / DCH;
  const int N = in_sizes[1] / DCH;
  const int E = in_sizes[4];

  float *qc, *nc, *accb, *agts1;
  unsigned char* wp;
  cudaGetSymbolAddress((void**)&qc,    g_qc);
  cudaGetSymbolAddress((void**)&nc,    g_nc);
  cudaGetSymbolAddress((void**)&accb,  g_acc);
  cudaGetSymbolAddress((void**)&agts1, g_agts);
  cudaGetSymbolAddress((void**)&wp,    g_wp);

  cudaFuncSetAttribute(mn_kernel, cudaFuncAttributeMaxDynamicSharedMemorySize, SMEM_SZ);
  cudaFuncSetAttribute(e_kernel,  cudaFuncAttributeMaxDynamicSharedMemorySize, SMEM_SZ);
  cudaFuncSetAttribute(f_kernel,  cudaFuncAttributeMaxDynamicSharedMemorySize, SMEM_SZ);

  const int mb = (M + TMR - 1) / TMR;
  const int nb = (N + TMR - 1) / TMR;
  const int eb = (E + TMR - 1) / TMR;

  wpack_kernel<<<16, 128>>>(Wq, Wc1, Wc2, Wa, Wl, Wd2, wp);

  const float* agts_in = actors;
  for (int L = 0; L < 2; L++) {
    P p = {};
    p.agts = agts_in;
    p.nodes = nodes;
    p.actor_ctrs = actor_ctrs;
    p.node_ctrs = node_ctrs;
    p.hi = hi;
    p.wi = wi;
    p.wp = wp + (size_t)L * 8 * SLAB_B;
    p.Wd1 = Wd1 + L * DCH * 2;
    p.bd1 = bd1 + L * DCH;
    p.gnq_w = gnqw + L * DCH;   p.gnq_b = gnqb + L * DCH;
    p.gnd2_w = gnd2w + L * DCH; p.gnd2_b = gnd2b + L * DCH;
    p.gnc1_w = gnc1w + L * DCH; p.gnc1_b = gnc1b + L * DCH;
    p.gnn_w = gnnw + L * DCH;   p.gnn_b = gnnb + L * DCH;
    p.gnl_w = gnlw + L * DCH;   p.gnl_b = gnlb + L * DCH;
    p.qc = qc; p.nc = nc; p.acc = accb;
    p.out = (L == 0) ? agts1 : (float*)d_out;
    p.M = M; p.N = N; p.E = E; p.mb = mb; p.nb = nb;

    mn_kernel<<<mb + nb + mb, 256, SMEM_SZ>>>(p);
    e_kernel<<<eb, 256, SMEM_SZ>>>(p);
    f_kernel<<<mb, 256, SMEM_SZ>>>(p);

    agts_in = agts1;
  }
}

// round 7
// speedup vs baseline: 2.3530x; 2.3530x over previous
#include <cuda_runtime.h>
#include <cuda_fp16.h>
#include <cstdint>

#define DCH 128
#define TMR 64
#define ROWB 272               // 256B data + 16B pad per row (16B aligned)

#define OFF_A   0
#define OFF_B   (64 * ROWB)                  // 17408
#define OFF_PS  (OFF_B + 128 * ROWB)         // 52224 : ps[4][64], pq[4][64]
#define SMEM_SZ (OFF_PS + 2048 + 64)

#define SLAB_B  (128 * 256)                  // fp16 plane, interleaved k-layout

// ---------------- scratch (alloc-free) ----------------
__device__ float g_qc[4000 * 128];
__device__ float g_nc[20000 * 128];
__device__ float g_acc[4000 * 128];
__device__ float g_agts[4000 * 128];
__device__ __align__(16) unsigned char g_wp[2 * 8 * SLAB_B];

// slabs: 0=Wq 1=Wc1a 2=Wc1b 3=Wc1c 4=Wc2 5=Wa 6=Wl 7=Wd2

struct P {
  const float* agts; const float* nodes;
  const float* actor_ctrs; const float* node_ctrs;
  const int* hi; const int* wi;
  const unsigned char* wp;
  const float* Wd1; const float* bd1;
  const float *gnq_w, *gnq_b, *gnd2_w, *gnd2_b, *gnc1_w, *gnc1_b,
              *gnn_w, *gnn_b, *gnl_w, *gnl_b;
  float *qc, *nc, *acc, *out;
  int M, N, E, mb, nb;
};

__device__ __forceinline__ uint32_t smem_u32(const void* p) {
  uint32_t a;
  asm("{ .reg .u64 t; cvta.to.shared.u64 t, %1; cvt.u32.u64 %0, t; }" : "=r"(a) : "l"(p));
  return a;
}
#define LDS64(x, y, addr) \
  asm volatile("ld.shared.v2.u32 {%0,%1}, [%2];" : "=r"(x), "=r"(y) : "r"(addr))
#define STS32(addr, v) \
  asm volatile("st.shared.u32 [%0], %1;" :: "r"(addr), "r"(v))

__device__ __forceinline__ uint32_t h2pack(float lo, float hi) {
  uint32_t r;
  asm("cvt.rn.f16x2.f32 %0, %1, %2;" : "=r"(r) : "f"(hi), "f"(lo));
  return r;
}

__device__ __forceinline__ void mma_h(float c[4], const uint32_t a[4],
                                      uint32_t b0, uint32_t b1) {
  asm volatile(
    "mma.sync.aligned.m16n8k16.row.col.f32.f16.f16.f32 "
    "{%0,%1,%2,%3}, {%4,%5,%6,%7}, {%8,%9}, {%0,%1,%2,%3};"
    : "+f"(c[0]), "+f"(c[1]), "+f"(c[2]), "+f"(c[3])
    : "r"(a[0]), "r"(a[1]), "r"(a[2]), "r"(a[3]), "r"(b0), "r"(b1));
}

// k-layout within each 32B group (16 cols): [k0k1 k8k9 | k2k3 k10k11 | k4k5 k12k13 | k6k7 k14k15]
// -> thread tg's LDS64 at group + tg*8 yields (2tg,2tg+1, 2tg+8,2tg+9)

// store 32 contiguous cols (v[0..31] = cols q*32..q*32+31) of row r
__device__ __forceinline__ void store_A_h(char* smem, const float v[32], int r, int q) {
  char* rowp = smem + OFF_A + r * ROWB;
#pragma unroll
  for (int g2 = 0; g2 < 2; g2++) {
    char* gp = rowp + (2 * q + g2) * 32;
#pragma unroll
    for (int a = 0; a < 4; a++) {
      uint2 o = make_uint2(h2pack(v[16 * g2 + 2 * a],     v[16 * g2 + 2 * a + 1]),
                           h2pack(v[16 * g2 + 2 * a + 8], v[16 * g2 + 2 * a + 9]));
      *(uint2*)(gp + a * 8) = o;
    }
  }
}

__device__ __forceinline__ void copy_B(char* smem, const unsigned char* wps) {
  const uint4* src = (const uint4*)wps;        // 2048 uint4
  for (int i = threadIdx.x; i < 2048; i += 256) {
    int row = i >> 4, u = i & 15;
    *(uint4*)(smem + OFF_B + row * ROWB + u * 16) = src[i];
  }
}

__device__ __forceinline__ void mainloop_h(const char* smem, float acc[2][4][4],
                                           int rowb, int cwb, int g, int tg) {
  const uint32_t Ab = smem_u32(smem) + OFF_A;
  const uint32_t Bb = smem_u32(smem) + OFF_B;
#pragma unroll
  for (int ms = 0; ms < 2; ms++)
#pragma unroll
    for (int ns = 0; ns < 4; ns++)
#pragma unroll
      for (int q = 0; q < 4; q++) acc[ms][ns][q] = 0.f;
#pragma unroll
  for (int ks = 0; ks < 8; ks++) {
    uint32_t a[2][4];
#pragma unroll
    for (int ms = 0; ms < 2; ms++) {
      const int r0 = rowb + ms * 16 + g;
      LDS64(a[ms][0], a[ms][2], Ab + r0 * ROWB + ks * 32 + tg * 8);
      LDS64(a[ms][1], a[ms][3], Ab + (r0 + 8) * ROWB + ks * 32 + tg * 8);
    }
#pragma unroll
    for (int ns = 0; ns < 4; ns++) {
      uint32_t b0, b1;
      LDS64(b0, b1, Bb + (cwb + ns * 8 + g) * ROWB + ks * 32 + tg * 8);
#pragma unroll
      for (int ms = 0; ms < 2; ms++)
        mma_h(acc[ms][ns], a[ms], b0, b1);
    }
  }
}

// GroupNorm (1 group, 128 ch) — one internal syncthreads
__device__ __forceinline__ void gn_ep(float f[2][4][4], char* smem,
                                      const float* gnw, const float* gnb,
                                      int rowb, int cwb, int nw, int g, int tg,
                                      bool dorelu) {
  float* ps = (float*)(smem + OFF_PS);
  float* pq = ps + 256;
#pragma unroll
  for (int ms = 0; ms < 2; ms++)
#pragma unroll
    for (int h = 0; h < 2; h++) {
      float s = 0.f, q = 0.f;
#pragma unroll
      for (int ns = 0; ns < 4; ns++)
#pragma unroll
        for (int j = 0; j < 2; j++) {
          float v = f[ms][ns][2 * h + j];
          s += v;
          q = fmaf(v, v, q);
        }
      s += __shfl_xor_sync(0xffffffffu, s, 1);
      q += __shfl_xor_sync(0xffffffffu, q, 1);
      s += __shfl_xor_sync(0xffffffffu, s, 2);
      q += __shfl_xor_sync(0xffffffffu, q, 2);
      const int r = rowb + ms * 16 + h * 8 + g;
      if (tg == 0) { ps[nw * 64 + r] = s; pq[nw * 64 + r] = q; }
    }
  __syncthreads();
  const int c0 = cwb + tg * 2;
  float2 gwv[4], gbv[4];
#pragma unroll
  for (int ns = 0; ns < 4; ns++) {
    gwv[ns] = *(const float2*)(gnw + c0 + ns * 8);
    gbv[ns] = *(const float2*)(gnb + c0 + ns * 8);
  }
#pragma unroll
  for (int ms = 0; ms < 2; ms++)
#pragma unroll
    for (int h = 0; h < 2; h++) {
      const int r = rowb + ms * 16 + h * 8 + g;
      float s = ps[r] + ps[64 + r] + ps[128 + r] + ps[192 + r];
      float q = pq[r] + pq[64 + r] + pq[128 + r] + pq[192 + r];
      float m = s * (1.f / DCH);
      float var = q * (1.f / DCH) - m * m;
      float inv = rsqrtf(var + 1e-5f);
#pragma unroll
      for (int ns = 0; ns < 4; ns++) {
        float a0 = fmaf((f[ms][ns][2 * h]     - m) * inv, gwv[ns].x, gbv[ns].x);
        float a1 = fmaf((f[ms][ns][2 * h + 1] - m) * inv, gwv[ns].y, gbv[ns].y);
        if (dorelu) { a0 = fmaxf(a0, 0.f); a1 = fmaxf(a1, 0.f); }
        f[ms][ns][2 * h]     = a0;
        f[ms][ns][2 * h + 1] = a1;
      }
    }
}

// write f back as next-stage A (fp16 interleaved layout); caller syncs after
__device__ __forceinline__ void repack_A(const float f[2][4][4], char* smem,
                                         int rowb, int cwb, int g, int tg) {
  const uint32_t Ab = smem_u32(smem) + OFF_A;
#pragma unroll
  for (int ms = 0; ms < 2; ms++)
#pragma unroll
    for (int h = 0; h < 2; h++) {
      const int r = rowb + ms * 16 + h * 8 + g;
#pragma unroll
      for (int ns = 0; ns < 4; ns++) {
        const int c = cwb + ns * 8 + tg * 2;
        const int ks = c >> 4, qq = (c & 15) >> 1;
        const int slot = 2 * (qq & 3) + (qq >> 2);
        STS32(Ab + r * ROWB + ks * 32 + slot * 4,
              h2pack(f[ms][ns][2 * h], f[ms][ns][2 * h + 1]));
      }
    }
}

__device__ __forceinline__ void store_plain(const float f[2][4][4], float* Y, int row0,
                                            int rows, int rowb, int cwb, int g, int tg) {
  const int c0 = cwb + tg * 2;
#pragma unroll
  for (int ms = 0; ms < 2; ms++)
#pragma unroll
    for (int h = 0; h < 2; h++) {
      const int gr = row0 + rowb + ms * 16 + h * 8 + g;
      if (gr < rows) {
        float* dst = Y + (size_t)gr * DCH + c0;
#pragma unroll
        for (int ns = 0; ns < 4; ns++)
          *(float2*)(dst + ns * 8) =
              make_float2(f[ms][ns][2 * h], f[ms][ns][2 * h + 1]);
      }
    }
}

__device__ __forceinline__ void load_A_h(char* smem, const float* X, int row0, int rows) {
  const int r = threadIdx.x >> 2, q = threadIdx.x & 3;
  const int gr = row0 + r;
  const float* px = X + (size_t)gr * DCH + q * 32;
  float v[32];
#pragma unroll
  for (int i = 0; i < 8; i++) {
    float4 t = (gr < rows) ? *(const float4*)(px + 4 * i) : make_float4(0.f, 0.f, 0.f, 0.f);
    v[4 * i] = t.x; v[4 * i + 1] = t.y; v[4 * i + 2] = t.z; v[4 * i + 3] = t.w;
  }
  store_A_h(smem, v, r, q);
}

// ---------------- weight pack (fp16, interleaved k-layout) ----------------
__global__ void wpack_kernel(const float* Wq, const float* Wc1, const float* Wc2,
                             const float* Wa, const float* Wl, const float* Wd2,
                             unsigned char* wp) {
  int L = blockIdx.x >> 3, s = blockIdx.x & 7;
  const float* src;
  int ldw = DCH, coff = 0;
  switch (s) {
    case 0: src = Wq  + (size_t)L * DCH * DCH; break;
    case 1: src = Wc1 + (size_t)L * DCH * 3 * DCH; ldw = 3 * DCH; coff = 0;       break;
    case 2: src = Wc1 + (size_t)L * DCH * 3 * DCH; ldw = 3 * DCH; coff = DCH;     break;
    case 3: src = Wc1 + (size_t)L * DCH * 3 * DCH; ldw = 3 * DCH; coff = 2 * DCH; break;
    case 4: src = Wc2 + (size_t)L * DCH * DCH; break;
    case 5: src = Wa  + (size_t)L * DCH * DCH; break;
    case 6: src = Wl  + (size_t)L * DCH * DCH; break;
    default: src = Wd2 + (size_t)L * DCH * DCH; break;
  }
  unsigned char* dst = wp + (size_t)(L * 8 + s) * SLAB_B;
  const int j = threadIdx.x;
  const float* wr = src + (size_t)j * ldw + coff;
#pragma unroll
  for (int ks = 0; ks < 8; ks++) {
#pragma unroll
    for (int a = 0; a < 4; a++) {
      uint2 o = make_uint2(
          h2pack(wr[ks * 16 + 2 * a],     wr[ks * 16 + 2 * a + 1]),
          h2pack(wr[ks * 16 + 2 * a + 8], wr[ks * 16 + 2 * a + 9]));
      *(uint2*)(dst + (size_t)j * 256 + ks * 32 + a * 8) = o;
    }
  }
}

// ---------------- MN mega-kernel: {Wq->Wc1b | nodes->Wc1c | Wa} ----------------
__global__ void __launch_bounds__(256, 3) mn_kernel(P p) {
  extern __shared__ char smem[];
  const int tid = threadIdx.x, warp = tid >> 5, lane = tid & 31;
  const int mw = warp & 1, nw = warp >> 1;
  const int rowb = mw * 32, cwb = nw * 32, g = lane >> 2, tg = lane & 3;
  const int b = blockIdx.x;
  float f[2][4][4];

  if (b < p.mb) {
    const int row0 = b * TMR;
    load_A_h(smem, p.agts, row0, p.M);
    copy_B(smem, p.wp + 0 * SLAB_B);             // Wq
    __syncthreads();
    mainloop_h(smem, f, rowb, cwb, g, tg);
    gn_ep(f, smem, p.gnq_w, p.gnq_b, rowb, cwb, nw, g, tg, true);
    repack_A(f, smem, rowb, cwb, g, tg);
    copy_B(smem, p.wp + 2 * SLAB_B);             // Wc1b
    __syncthreads();
    mainloop_h(smem, f, rowb, cwb, g, tg);
    store_plain(f, p.qc, row0, p.M, rowb, cwb, g, tg);
  } else if (b < p.mb + p.nb) {
    const int row0 = (b - p.mb) * TMR;
    load_A_h(smem, p.nodes, row0, p.N);
    copy_B(smem, p.wp + 3 * SLAB_B);             // Wc1c
    __syncthreads();
    mainloop_h(smem, f, rowb, cwb, g, tg);
    store_plain(f, p.nc, row0, p.N, rowb, cwb, g, tg);
  } else {
    const int row0 = (b - p.mb - p.nb) * TMR;
    load_A_h(smem, p.agts, row0, p.M);
    copy_B(smem, p.wp + 5 * SLAB_B);             // Wa
    __syncthreads();
    mainloop_h(smem, f, rowb, cwb, g, tg);
    store_plain(f, p.acc, row0, p.M, rowb, cwb, g, tg);
  }
}

// ---------------- E kernel: fused dist-MLP -> ctx-MLP -> scatter ----------------
__global__ void __launch_bounds__(256, 3) e_kernel(P p) {
  extern __shared__ char smem[];
  const int tid = threadIdx.x, warp = tid >> 5, lane = tid & 31;
  const int mw = warp & 1, nw = warp >> 1;
  const int rowb = mw * 32, cwb = nw * 32, g = lane >> 2, tg = lane & 3;
  const int row0 = blockIdx.x * TMR;
  float f[2][4][4];

  // stage 1: A = relu(ctr_d @ Wd1^T + bd1), B = Wd2
  {
    const int r = tid >> 2, q = tid & 3;
    const int gr = row0 + r;
    float cx = 0.f, cy = 0.f;
    if (gr < p.E) {
      int h = p.hi[gr], w = p.wi[gr];
      cx = p.actor_ctrs[2 * h]     - p.node_ctrs[2 * w];
      cy = p.actor_ctrs[2 * h + 1] - p.node_ctrs[2 * w + 1];
    }
    float v[32];
#pragma unroll
    for (int i = 0; i < 32; i++) {
      const int k = q * 32 + i;
      v[i] = fmaxf(fmaf(cx, p.Wd1[2 * k], fmaf(cy, p.Wd1[2 * k + 1], p.bd1[k])), 0.f);
    }
    store_A_h(smem, v, r, q);
  }
  copy_B(smem, p.wp + 7 * SLAB_B);               // Wd2
  __syncthreads();
  mainloop_h(smem, f, rowb, cwb, g, tg);
  gn_ep(f, smem, p.gnd2_w, p.gnd2_b, rowb, cwb, nw, g, tg, true);
  repack_A(f, smem, rowb, cwb, g, tg);
  copy_B(smem, p.wp + 1 * SLAB_B);               // Wc1a
  __syncthreads();

  // stage 2: + qc[hi] + nc[wi], gn, relu
  mainloop_h(smem, f, rowb, cwb, g, tg);
  {
    const int c0 = cwb + tg * 2;
#pragma unroll
    for (int ms = 0; ms < 2; ms++)
#pragma unroll
      for (int h = 0; h < 2; h++) {
        const int gr = row0 + rowb + ms * 16 + h * 8 + g;
        if (gr < p.E) {
          const float* p1 = p.qc + (size_t)p.hi[gr] * DCH + c0;
          const float* p2 = p.nc + (size_t)p.wi[gr] * DCH + c0;
#pragma unroll
          for (int ns = 0; ns < 4; ns++) {
            float2 v1 = *(const float2*)(p1 + ns * 8);
            float2 v2 = *(const float2*)(p2 + ns * 8);
            f[ms][ns][2 * h]     += v1.x + v2.x;
            f[ms][ns][2 * h + 1] += v1.y + v2.y;
          }
        }
      }
  }
  gn_ep(f, smem, p.gnc1_w, p.gnc1_b, rowb, cwb, nw, g, tg, true);
  repack_A(f, smem, rowb, cwb, g, tg);
  copy_B(smem, p.wp + 4 * SLAB_B);               // Wc2
  __syncthreads();

  // stage 3: acc[hi] += cf @ Wc2^T  (atomic scatter)
  mainloop_h(smem, f, rowb, cwb, g, tg);
  {
    const int c0 = cwb + tg * 2;
#pragma unroll
    for (int ms = 0; ms < 2; ms++)
#pragma unroll
      for (int h = 0; h < 2; h++) {
        const int gr = row0 + rowb + ms * 16 + h * 8 + g;
        if (gr < p.E) {
          float* dst = p.acc + (size_t)p.hi[gr] * DCH + c0;
#pragma unroll
          for (int ns = 0; ns < 4; ns++) {
            atomicAdd(dst + ns * 8,     f[ms][ns][2 * h]);
            atomicAdd(dst + ns * 8 + 1, f[ms][ns][2 * h + 1]);
          }
        }
      }
  }
}

// ---------------- F kernel: relu(gn(acc)) -> Wl -> gn + residual + relu ----------------
__global__ void __launch_bounds__(256, 3) f_kernel(P p) {
  extern __shared__ char smem[];
  const int tid = threadIdx.x, warp = tid >> 5, lane = tid & 31;
  const int mw = warp & 1, nw = warp >> 1;
  const int rowb = mw * 32, cwb = nw * 32, g = lane >> 2, tg = lane & 3;
  const int row0 = blockIdx.x * TMR;
  float f[2][4][4];

  {
    const int r = tid >> 2, q = tid & 3;
    const int gr = row0 + r;
    float v[32];
    const float* px = p.acc + (size_t)gr * DCH + q * 32;
#pragma unroll
    for (int i = 0; i < 8; i++) {
      float4 t = (gr < p.M) ? *(const float4*)(px + 4 * i) : make_float4(0.f, 0.f, 0.f, 0.f);
      v[4 * i] = t.x; v[4 * i + 1] = t.y; v[4 * i + 2] = t.z; v[4 * i + 3] = t.w;
    }
    float s = 0.f, qq = 0.f;
#pragma unroll
    for (int i = 0; i < 32; i++) { s += v[i]; qq = fmaf(v[i], v[i], qq); }
    s  += __shfl_xor_sync(0xffffffffu, s, 1);
    qq += __shfl_xor_sync(0xffffffffu, qq, 1);
    s  += __shfl_xor_sync(0xffffffffu, s, 2);
    qq += __shfl_xor_sync(0xffffffffu, qq, 2);
    float m = s * (1.f / DCH);
    float var = qq * (1.f / DCH) - m * m;
    float inv = rsqrtf(var + 1e-5f);
#pragma unroll
    for (int i = 0; i < 32; i++) {
      const int c = q * 32 + i;
      v[i] = fmaxf(fmaf((v[i] - m) * inv, p.gnn_w[c], p.gnn_b[c]), 0.f);
    }
    store_A_h(smem, v, r, q);
  }
  copy_B(smem, p.wp + 6 * SLAB_B);               // Wl
  __syncthreads();
  mainloop_h(smem, f, rowb, cwb, g, tg);
  gn_ep(f, smem, p.gnl_w, p.gnl_b, rowb, cwb, nw, g, tg, false);
  {
    const int c0 = cwb + tg * 2;
#pragma unroll
    for (int ms = 0; ms < 2; ms++)
#pragma unroll
      for (int h = 0; h < 2; h++) {
        const int gr = row0 + rowb + ms * 16 + h * 8 + g;
        if (gr < p.M) {
          const float* rp = p.agts + (size_t)gr * DCH + c0;
          float* dst = p.out + (size_t)gr * DCH + c0;
#pragma unroll
          for (int ns = 0; ns < 4; ns++) {
            float2 rv = *(const float2*)(rp + ns * 8);
            *(float2*)(dst + ns * 8) =
                make_float2(fmaxf(f[ms][ns][2 * h]     + rv.x, 0.f),
                            fmaxf(f[ms][ns][2 * h + 1] + rv.y, 0.f));
          }
        }
      }
  }
}

extern "C" void kernel_launch(void* const* d_in, const int* in_sizes, int n_in,
                              void* d_out, int out_size) {
  const float* actors     = (const float*)d_in[0];
  const float* nodes      = (const float*)d_in[1];
  const float* actor_ctrs = (const float*)d_in[2];
  const float* node_ctrs  = (const float*)d_in[3];
  const int*   hi         = (const int*)d_in[4];
  const int*   wi         = (const int*)d_in[5];
  const float* Wd1   = (const float*)d_in[6];
  const float* bd1   = (const float*)d_in[7];
  const float* Wd2   = (const float*)d_in[8];
  const float* gnd2w = (const float*)d_in[9];
  const float* gnd2b = (const float*)d_in[10];
  const float* Wq    = (const float*)d_in[11];
  const float* gnqw  = (const float*)d_in[12];
  const float* gnqb  = (const float*)d_in[13];
  const float* Wc1   = (const float*)d_in[14];
  const float* gnc1w = (const float*)d_in[15];
  const float* gnc1b = (const float*)d_in[16];
  const float* Wc2   = (const float*)d_in[17];
  const float* Wa    = (const float*)d_in[18];
  const float* gnnw  = (const float*)d_in[19];
  const float* gnnb  = (const float*)d_in[20];
  const float* Wl    = (const float*)d_in[21];
  const float* gnlw  = (const float*)d_in[22];
  const float* gnlb  = (const float*)d_in[23];

  const int M = in_sizes[0] / DCH;
  const int N = in_sizes[1] / DCH;
  const int E = in_sizes[4];

  float *qc, *nc, *accb, *agts1;
  unsigned char* wp;
  cudaGetSymbolAddress((void**)&qc,    g_qc);
  cudaGetSymbolAddress((void**)&nc,    g_nc);
  cudaGetSymbolAddress((void**)&accb,  g_acc);
  cudaGetSymbolAddress((void**)&agts1, g_agts);
  cudaGetSymbolAddress((void**)&wp,    g_wp);

  cudaFuncSetAttribute(mn_kernel, cudaFuncAttributeMaxDynamicSharedMemorySize, SMEM_SZ);
  cudaFuncSetAttribute(e_kernel,  cudaFuncAttributeMaxDynamicSharedMemorySize, SMEM_SZ);
  cudaFuncSetAttribute(f_kernel,  cudaFuncAttributeMaxDynamicSharedMemorySize, SMEM_SZ);

  const int mb = (M + TMR - 1) / TMR;
  const int nb = (N + TMR - 1) / TMR;
  const int eb = (E + TMR - 1) / TMR;

  wpack_kernel<<<16, 128>>>(Wq, Wc1, Wc2, Wa, Wl, Wd2, wp);

  const float* agts_in = actors;
  for (int L = 0; L < 2; L++) {
    P p = {};
    p.agts = agts_in;
    p.nodes = nodes;
    p.actor_ctrs = actor_ctrs;
    p.node_ctrs = node_ctrs;
    p.hi = hi;
    p.wi = wi;
    p.wp = wp + (size_t)L * 8 * SLAB_B;
    p.Wd1 = Wd1 + L * DCH * 2;
    p.bd1 = bd1 + L * DCH;
    p.gnq_w = gnqw + L * DCH;   p.gnq_b = gnqb + L * DCH;
    p.gnd2_w = gnd2w + L * DCH; p.gnd2_b = gnd2b + L * DCH;
    p.gnc1_w = gnc1w + L * DCH; p.gnc1_b = gnc1b + L * DCH;
    p.gnn_w = gnnw + L * DCH;   p.gnn_b = gnnb + L * DCH;
    p.gnl_w = gnlw + L * DCH;   p.gnl_b = gnlb + L * DCH;
    p.qc = qc; p.nc = nc; p.acc = accb;
    p.out = (L == 0) ? agts1 : (float*)d_out;
    p.M = M; p.N = N; p.E = E; p.mb = mb; p.nb = nb;

    mn_kernel<<<mb + nb + mb, 256, SMEM_SZ>>>(p);
    e_kernel<<<eb, 256, SMEM_SZ>>>(p);
    f_kernel<<<mb, 256, SMEM_SZ>>>(p);

    agts_in = agts1;
  }
}

// round 8
// speedup vs baseline: 3.0089x; 1.2788x over previous
#include <cuda_runtime.h>
#include <cuda_fp16.h>
#include <cstdint>

#define DCH 128
#define TMR 128
#define ROWB 272               // 256B data + 16B pad

#define OFF_A   0
#define OFF_B0  (128 * ROWB)                 // 34816
#define OFF_B1  (2 * 128 * ROWB)             // 69632
#define OFF_PS  (3 * 128 * ROWB)             // 104448 : ps[2][128], pq[2][128]
#define SMEM_SZ (OFF_PS + 2048 + 64)

#define SLAB_B  (128 * 256)                  // fp16 row-major weight plane

// ---------------- scratch (alloc-free) ----------------
__device__ float g_qc[4000 * 128];
__device__ float g_nc[20000 * 128];
__device__ float g_acc[4000 * 128];
__device__ float g_agts[4000 * 128];
__device__ __align__(16) unsigned char g_wp[2 * 8 * SLAB_B];

// slabs: 0=Wq 1=Wc1a 2=Wc1b 3=Wc1c 4=Wc2 5=Wa 6=Wl 7=Wd2

struct P {
  const float* agts; const float* nodes;
  const float* actor_ctrs; const float* node_ctrs;
  const int* hi; const int* wi;
  const unsigned char* wp;
  const float* Wd1; const float* bd1;
  const float *gnq_w, *gnq_b, *gnd2_w, *gnd2_b, *gnc1_w, *gnc1_b,
              *gnn_w, *gnn_b, *gnl_w, *gnl_b;
  float *qc, *nc, *acc, *out;
  int M, N, E, mb, nb;
};

__device__ __forceinline__ uint32_t smem_u32(const void* p) {
  uint32_t a;
  asm("{ .reg .u64 t; cvta.to.shared.u64 t, %1; cvt.u32.u64 %0, t; }" : "=r"(a) : "l"(p));
  return a;
}
#define LDSM4(r0, r1, r2, r3, addr) \
  asm volatile("ldmatrix.sync.aligned.m8n8.x4.shared.b16 {%0,%1,%2,%3}, [%4];" \
    : "=r"(r0), "=r"(r1), "=r"(r2), "=r"(r3) : "r"(addr))
#define STS32(addr, v) \
  asm volatile("st.shared.u32 [%0], %1;" :: "r"(addr), "r"(v))
#define CP_A16(dst, src) \
  asm volatile("cp.async.cg.shared.global [%0], [%1], 16;" :: "r"(dst), "l"(src))
#define CP_COMMIT() asm volatile("cp.async.commit_group;" ::: "memory")
#define CP_WAIT(n)  asm volatile("cp.async.wait_group %0;" :: "n"(n) : "memory")

__device__ __forceinline__ uint32_t h2pack(float lo, float hi) {
  uint32_t r;
  asm("cvt.rn.f16x2.f32 %0, %1, %2;" : "=r"(r) : "f"(hi), "f"(lo));
  return r;
}

__device__ __forceinline__ void mma_h(float c[4], const uint32_t a[4],
                                      uint32_t b0, uint32_t b1) {
  asm volatile(
    "mma.sync.aligned.m16n8k16.row.col.f32.f16.f16.f32 "
    "{%0,%1,%2,%3}, {%4,%5,%6,%7}, {%8,%9}, {%0,%1,%2,%3};"
    : "+f"(c[0]), "+f"(c[1]), "+f"(c[2]), "+f"(c[3])
    : "r"(a[0]), "r"(a[1]), "r"(a[2]), "r"(a[3]), "r"(b0), "r"(b1));
}

// store 32 contiguous cols of row r (plain row-major fp16)
__device__ __forceinline__ void store_A_h(char* smem, const float v[32], int r, int q) {
  char* rowp = smem + OFF_A + r * ROWB + q * 64;
#pragma unroll
  for (int a = 0; a < 4; a++) {
    uint4 o = make_uint4(h2pack(v[8 * a],     v[8 * a + 1]),
                         h2pack(v[8 * a + 2], v[8 * a + 3]),
                         h2pack(v[8 * a + 4], v[8 * a + 5]),
                         h2pack(v[8 * a + 6], v[8 * a + 7]));
    *(uint4*)(rowp + a * 16) = o;
  }
}

// async copy of a 128x256B weight plane into smem buffer (caller commits)
__device__ __forceinline__ void copy_B_async(char* smem, int bOff, const unsigned char* wps) {
  const uint32_t dst = smem_u32(smem) + bOff;
  for (int i = threadIdx.x; i < 2048; i += 256) {
    int row = i >> 4, u = i & 15;
    CP_A16(dst + row * ROWB + u * 16, wps + (size_t)i * 16);
  }
  CP_COMMIT();
}

// 128x128x128 fused-tile mainloop via ldmatrix
__device__ __forceinline__ void mainloop_h(const char* smem, int bOff, float acc[2][8][4],
                                           int rowb, int cwb, int lane) {
  const uint32_t Ab = smem_u32(smem) + OFF_A;
  const uint32_t Bb = smem_u32(smem) + bOff;
  const uint32_t aAddr = Ab + (rowb + (lane & 15)) * ROWB + ((lane >> 4) << 4);
  const uint32_t bAddr = Bb + (cwb + ((lane >> 4) << 3) + (lane & 7)) * ROWB
                            + ((lane & 8) ? 16 : 0);
#pragma unroll
  for (int ms = 0; ms < 2; ms++)
#pragma unroll
    for (int ns = 0; ns < 8; ns++)
#pragma unroll
      for (int q = 0; q < 4; q++) acc[ms][ns][q] = 0.f;
#pragma unroll
  for (int ks = 0; ks < 8; ks++) {
    uint32_t a[2][4], b[4][4];
    LDSM4(a[0][0], a[0][1], a[0][2], a[0][3], aAddr + ks * 32);
    LDSM4(a[1][0], a[1][1], a[1][2], a[1][3], aAddr + 16 * ROWB + ks * 32);
#pragma unroll
    for (int pr = 0; pr < 4; pr++)
      LDSM4(b[pr][0], b[pr][1], b[pr][2], b[pr][3], bAddr + pr * 16 * ROWB + ks * 32);
#pragma unroll
    for (int ns = 0; ns < 8; ns++) {
      uint32_t b0 = b[ns >> 1][(ns & 1) * 2], b1 = b[ns >> 1][(ns & 1) * 2 + 1];
      mma_h(acc[0][ns], a[0], b0, b1);
      mma_h(acc[1][ns], a[1], b0, b1);
    }
  }
}

// GroupNorm (1 group, 128 ch) — one internal syncthreads
__device__ __forceinline__ void gn_ep(float f[2][8][4], char* smem,
                                      const float* gnw, const float* gnb,
                                      int rowb, int cwb, int nw, int g, int tg,
                                      bool dorelu) {
  float* ps = (float*)(smem + OFF_PS);      // [2][128]
  float* pq = ps + 256;
#pragma unroll
  for (int ms = 0; ms < 2; ms++)
#pragma unroll
    for (int h = 0; h < 2; h++) {
      float s = 0.f, q = 0.f;
#pragma unroll
      for (int ns = 0; ns < 8; ns++)
#pragma unroll
        for (int j = 0; j < 2; j++) {
          float v = f[ms][ns][2 * h + j];
          s += v;
          q = fmaf(v, v, q);
        }
      s += __shfl_xor_sync(0xffffffffu, s, 1);
      q += __shfl_xor_sync(0xffffffffu, q, 1);
      s += __shfl_xor_sync(0xffffffffu, s, 2);
      q += __shfl_xor_sync(0xffffffffu, q, 2);
      const int r = rowb + ms * 16 + h * 8 + g;
      if (tg == 0) { ps[nw * 128 + r] = s; pq[nw * 128 + r] = q; }
    }
  __syncthreads();
  const int c0 = cwb + tg * 2;
#pragma unroll
  for (int ms = 0; ms < 2; ms++)
#pragma unroll
    for (int h = 0; h < 2; h++) {
      const int r = rowb + ms * 16 + h * 8 + g;
      float s = ps[r] + ps[128 + r];
      float q = pq[r] + pq[128 + r];
      float m = s * (1.f / DCH);
      float var = q * (1.f / DCH) - m * m;
      float inv = rsqrtf(var + 1e-5f);
#pragma unroll
      for (int ns = 0; ns < 8; ns++) {
        float2 gw = *(const float2*)(gnw + c0 + ns * 8);
        float2 gb = *(const float2*)(gnb + c0 + ns * 8);
        float a0 = fmaf((f[ms][ns][2 * h]     - m) * inv, gw.x, gb.x);
        float a1 = fmaf((f[ms][ns][2 * h + 1] - m) * inv, gw.y, gb.y);
        if (dorelu) { a0 = fmaxf(a0, 0.f); a1 = fmaxf(a1, 0.f); }
        f[ms][ns][2 * h]     = a0;
        f[ms][ns][2 * h + 1] = a1;
      }
    }
}

// write f back as next-stage A (row-major fp16); caller syncs after
__device__ __forceinline__ void repack_A(const float f[2][8][4], char* smem,
                                         int rowb, int cwb, int g, int tg) {
  const uint32_t Ab = smem_u32(smem) + OFF_A;
#pragma unroll
  for (int ms = 0; ms < 2; ms++)
#pragma unroll
    for (int h = 0; h < 2; h++) {
      const int r = rowb + ms * 16 + h * 8 + g;
#pragma unroll
      for (int ns = 0; ns < 8; ns++) {
        const int c = cwb + ns * 8 + tg * 2;
        STS32(Ab + r * ROWB + c * 2, h2pack(f[ms][ns][2 * h], f[ms][ns][2 * h + 1]));
      }
    }
}

__device__ __forceinline__ void store_plain(const float f[2][8][4], float* Y, int row0,
                                            int rows, int rowb, int cwb, int g, int tg) {
  const int c0 = cwb + tg * 2;
#pragma unroll
  for (int ms = 0; ms < 2; ms++)
#pragma unroll
    for (int h = 0; h < 2; h++) {
      const int gr = row0 + rowb + ms * 16 + h * 8 + g;
      if (gr < rows) {
        float* dst = Y + (size_t)gr * DCH + c0;
#pragma unroll
        for (int ns = 0; ns < 8; ns++)
          *(float2*)(dst + ns * 8) =
              make_float2(f[ms][ns][2 * h], f[ms][ns][2 * h + 1]);
      }
    }
}

__device__ __forceinline__ void load_A_h(char* smem, const float* X, int row0, int rows) {
  const int q = threadIdx.x & 3;
  for (int r = threadIdx.x >> 2; r < TMR; r += 64) {
    const int gr = row0 + r;
    const float* px = X + (size_t)gr * DCH + q * 32;
    float v[32];
#pragma unroll
    for (int i = 0; i < 8; i++) {
      float4 t = (gr < rows) ? *(const float4*)(px + 4 * i) : make_float4(0.f, 0.f, 0.f, 0.f);
      v[4 * i] = t.x; v[4 * i + 1] = t.y; v[4 * i + 2] = t.z; v[4 * i + 3] = t.w;
    }
    store_A_h(smem, v, r, q);
  }
}

// ---------------- weight pack (fp16 row-major plane) ----------------
__global__ void wpack_kernel(const float* Wq, const float* Wc1, const float* Wc2,
                             const float* Wa, const float* Wl, const float* Wd2,
                             unsigned char* wp) {
  int L = blockIdx.x >> 3, s = blockIdx.x & 7;
  const float* src;
  int ldw = DCH, coff = 0;
  switch (s) {
    case 0: src = Wq  + (size_t)L * DCH * DCH; break;
    case 1: src = Wc1 + (size_t)L * DCH * 3 * DCH; ldw = 3 * DCH; coff = 0;       break;
    case 2: src = Wc1 + (size_t)L * DCH * 3 * DCH; ldw = 3 * DCH; coff = DCH;     break;
    case 3: src = Wc1 + (size_t)L * DCH * 3 * DCH; ldw = 3 * DCH; coff = 2 * DCH; break;
    case 4: src = Wc2 + (size_t)L * DCH * DCH; break;
    case 5: src = Wa  + (size_t)L * DCH * DCH; break;
    case 6: src = Wl  + (size_t)L * DCH * DCH; break;
    default: src = Wd2 + (size_t)L * DCH * DCH; break;
  }
  unsigned char* dst = wp + (size_t)(L * 8 + s) * SLAB_B;
  const int j = threadIdx.x;
  const float* wr = src + (size_t)j * ldw + coff;
#pragma unroll
  for (int a = 0; a < 16; a++) {
    uint2 o = make_uint2(h2pack(wr[8 * a],     wr[8 * a + 1]),
                         h2pack(wr[8 * a + 2], wr[8 * a + 3]));
    uint2 o2 = make_uint2(h2pack(wr[8 * a + 4], wr[8 * a + 5]),
                          h2pack(wr[8 * a + 6], wr[8 * a + 7]));
    *(uint4*)(dst + (size_t)j * 256 + a * 16) = make_uint4(o.x, o.y, o2.x, o2.y);
  }
}

// ---------------- MN mega-kernel: {Wq->Wc1b | nodes->Wc1c | Wa} ----------------
__global__ void __launch_bounds__(256, 2) mn_kernel(P p) {
  extern __shared__ char smem[];
  const int tid = threadIdx.x, warp = tid >> 5, lane = tid & 31;
  const int mw = warp & 3, nw = warp >> 2;
  const int rowb = mw * 32, cwb = nw * 64, g = lane >> 2, tg = lane & 3;
  const int b = blockIdx.x;
  float f[2][8][4];

  if (b < p.mb) {
    const int row0 = b * TMR;
    copy_B_async(smem, OFF_B0, p.wp + 0 * SLAB_B);   // Wq     (group0)
    copy_B_async(smem, OFF_B1, p.wp + 2 * SLAB_B);   // Wc1b   (group1)
    load_A_h(smem, p.agts, row0, p.M);
    CP_WAIT(1);
    __syncthreads();
    mainloop_h(smem, OFF_B0, f, rowb, cwb, lane);
    gn_ep(f, smem, p.gnq_w, p.gnq_b, rowb, cwb, nw, g, tg, true);
    repack_A(f, smem, rowb, cwb, g, tg);
    CP_WAIT(0);
    __syncthreads();
    mainloop_h(smem, OFF_B1, f, rowb, cwb, lane);
    store_plain(f, p.qc, row0, p.M, rowb, cwb, g, tg);
  } else if (b < p.mb + p.nb) {
    const int row0 = (b - p.mb) * TMR;
    copy_B_async(smem, OFF_B0, p.wp + 3 * SLAB_B);   // Wc1c
    load_A_h(smem, p.nodes, row0, p.N);
    CP_WAIT(0);
    __syncthreads();
    mainloop_h(smem, OFF_B0, f, rowb, cwb, lane);
    store_plain(f, p.nc, row0, p.N, rowb, cwb, g, tg);
  } else {
    const int row0 = (b - p.mb - p.nb) * TMR;
    copy_B_async(smem, OFF_B0, p.wp + 5 * SLAB_B);   // Wa
    load_A_h(smem, p.agts, row0, p.M);
    CP_WAIT(0);
    __syncthreads();
    mainloop_h(smem, OFF_B0, f, rowb, cwb, lane);
    store_plain(f, p.acc, row0, p.M, rowb, cwb, g, tg);
  }
}

// ---------------- E kernel: fused dist-MLP -> ctx-MLP -> scatter ----------------
__global__ void __launch_bounds__(256, 2) e_kernel(P p) {
  extern __shared__ char smem[];
  const int tid = threadIdx.x, warp = tid >> 5, lane = tid & 31;
  const int mw = warp & 3, nw = warp >> 2;
  const int rowb = mw * 32, cwb = nw * 64, g = lane >> 2, tg = lane & 3;
  const int row0 = blockIdx.x * TMR;
  float f[2][8][4];

  copy_B_async(smem, OFF_B0, p.wp + 7 * SLAB_B);     // Wd2   (group0)
  copy_B_async(smem, OFF_B1, p.wp + 1 * SLAB_B);     // Wc1a  (group1)

  // stage 1 A: relu(ctr_d @ Wd1^T + bd1)
  {
    const int q = tid & 3;
    for (int r = tid >> 2; r < TMR; r += 64) {
      const int gr = row0 + r;
      float cx = 0.f, cy = 0.f;
      if (gr < p.E) {
        int h = p.hi[gr], w = p.wi[gr];
        cx = p.actor_ctrs[2 * h]     - p.node_ctrs[2 * w];
        cy = p.actor_ctrs[2 * h + 1] - p.node_ctrs[2 * w + 1];
      }
      float v[32];
#pragma unroll
      for (int i = 0; i < 32; i++) {
        const int k = q * 32 + i;
        v[i] = fmaxf(fmaf(cx, p.Wd1[2 * k], fmaf(cy, p.Wd1[2 * k + 1], p.bd1[k])), 0.f);
      }
      store_A_h(smem, v, r, q);
    }
  }
  CP_WAIT(1);
  __syncthreads();
  mainloop_h(smem, OFF_B0, f, rowb, cwb, lane);
  gn_ep(f, smem, p.gnd2_w, p.gnd2_b, rowb, cwb, nw, g, tg, true);
  copy_B_async(smem, OFF_B0, p.wp + 4 * SLAB_B);     // Wc2   (group2)
  repack_A(f, smem, rowb, cwb, g, tg);
  CP_WAIT(1);
  __syncthreads();

  // stage 2: + qc[hi] + nc[wi], gn, relu
  mainloop_h(smem, OFF_B1, f, rowb, cwb, lane);
  {
    const int c0 = cwb + tg * 2;
#pragma unroll
    for (int ms = 0; ms < 2; ms++)
#pragma unroll
      for (int h = 0; h < 2; h++) {
        const int gr = row0 + rowb + ms * 16 + h * 8 + g;
        if (gr < p.E) {
          const float* p1 = p.qc + (size_t)p.hi[gr] * DCH + c0;
          const float* p2 = p.nc + (size_t)p.wi[gr] * DCH + c0;
#pragma unroll
          for (int ns = 0; ns < 8; ns++) {
            float2 v1 = *(const float2*)(p1 + ns * 8);
            float2 v2 = *(const float2*)(p2 + ns * 8);
            f[ms][ns][2 * h]     += v1.x + v2.x;
            f[ms][ns][2 * h + 1] += v1.y + v2.y;
          }
        }
      }
  }
  gn_ep(f, smem, p.gnc1_w, p.gnc1_b, rowb, cwb, nw, g, tg, true);
  repack_A(f, smem, rowb, cwb, g, tg);
  CP_WAIT(0);
  __syncthreads();

  // stage 3: acc[hi] += cf @ Wc2^T  (atomic scatter)
  mainloop_h(smem, OFF_B0, f, rowb, cwb, lane);
  {
    const int c0 = cwb + tg * 2;
#pragma unroll
    for (int ms = 0; ms < 2; ms++)
#pragma unroll
      for (int h = 0; h < 2; h++) {
        const int gr = row0 + rowb + ms * 16 + h * 8 + g;
        if (gr < p.E) {
          float* dst = p.acc + (size_t)p.hi[gr] * DCH + c0;
#pragma unroll
          for (int ns = 0; ns < 8; ns++) {
            atomicAdd(dst + ns * 8,     f[ms][ns][2 * h]);
            atomicAdd(dst + ns * 8 + 1, f[ms][ns][2 * h + 1]);
          }
        }
      }
  }
}

// ---------------- F kernel: relu(gn(acc)) -> Wl -> gn + residual + relu ----------------
__global__ void __launch_bounds__(256, 2) f_kernel(P p) {
  extern __shared__ char smem[];
  const int tid = threadIdx.x, warp = tid >> 5, lane = tid & 31;
  const int mw = warp & 3, nw = warp >> 2;
  const int rowb = mw * 32, cwb = nw * 64, g = lane >> 2, tg = lane & 3;
  const int row0 = blockIdx.x * TMR;
  float f[2][8][4];

  copy_B_async(smem, OFF_B0, p.wp + 6 * SLAB_B);     // Wl
  {
    const int q = tid & 3;
    for (int r = tid >> 2; r < TMR; r += 64) {
      const int gr = row0 + r;
      float v[32];
      const float* px = p.acc + (size_t)gr * DCH + q * 32;
#pragma unroll
      for (int i = 0; i < 8; i++) {
        float4 t = (gr < p.M) ? *(const float4*)(px + 4 * i) : make_float4(0.f, 0.f, 0.f, 0.f);
        v[4 * i] = t.x; v[4 * i + 1] = t.y; v[4 * i + 2] = t.z; v[4 * i + 3] = t.w;
      }
      float s = 0.f, qq = 0.f;
#pragma unroll
      for (int i = 0; i < 32; i++) { s += v[i]; qq = fmaf(v[i], v[i], qq); }
      s  += __shfl_xor_sync(0xffffffffu, s, 1);
      qq += __shfl_xor_sync(0xffffffffu, qq, 1);
      s  += __shfl_xor_sync(0xffffffffu, s, 2);
      qq += __shfl_xor_sync(0xffffffffu, qq, 2);
      float m = s * (1.f / DCH);
      float var = qq * (1.f / DCH) - m * m;
      float inv = rsqrtf(var + 1e-5f);
#pragma unroll
      for (int i = 0; i < 32; i++) {
        const int c = q * 32 + i;
        v[i] = fmaxf(fmaf((v[i] - m) * inv, p.gnn_w[c], p.gnn_b[c]), 0.f);
      }
      store_A_h(smem, v, r, q);
    }
  }
  CP_WAIT(0);
  __syncthreads();
  mainloop_h(smem, OFF_B0, f, rowb, cwb, lane);
  gn_ep(f, smem, p.gnl_w, p.gnl_b, rowb, cwb, nw, g, tg, false);
  {
    const int c0 = cwb + tg * 2;
#pragma unroll
    for (int ms = 0; ms < 2; ms++)
#pragma unroll
      for (int h = 0; h < 2; h++) {
        const int gr = row0 + rowb + ms * 16 + h * 8 + g;
        if (gr < p.M) {
          const float* rp = p.agts + (size_t)gr * DCH + c0;
          float* dst = p.out + (size_t)gr * DCH + c0;
#pragma unroll
          for (int ns = 0; ns < 8; ns++) {
            float2 rv = *(const float2*)(rp + ns * 8);
            *(float2*)(dst + ns * 8) =
                make_float2(fmaxf(f[ms][ns][2 * h]     + rv.x, 0.f),
                            fmaxf(f[ms][ns][2 * h + 1] + rv.y, 0.f));
          }
        }
      }
  }
}

extern "C" void kernel_launch(void* const* d_in, const int* in_sizes, int n_in,
                              void* d_out, int out_size) {
  const float* actors     = (const float*)d_in[0];
  const float* nodes      = (const float*)d_in[1];
  const float* actor_ctrs = (const float*)d_in[2];
  const float* node_ctrs  = (const float*)d_in[3];
  const int*   hi         = (const int*)d_in[4];
  const int*   wi         = (const int*)d_in[5];
  const float* Wd1   = (const float*)d_in[6];
  const float* bd1   = (const float*)d_in[7];
  const float* Wd2   = (const float*)d_in[8];
  const float* gnd2w = (const float*)d_in[9];
  const float* gnd2b = (const float*)d_in[10];
  const float* Wq    = (const float*)d_in[11];
  const float* gnqw  = (const float*)d_in[12];
  const float* gnqb  = (const float*)d_in[13];
  const float* Wc1   = (const float*)d_in[14];
  const float* gnc1w = (const float*)d_in[15];
  const float* gnc1b = (const float*)d_in[16];
  const float* Wc2   = (const float*)d_in[17];
  const float* Wa    = (const float*)d_in[18];
  const float* gnnw  = (const float*)d_in[19];
  const float* gnnb  = (const float*)d_in[20];
  const float* Wl    = (const float*)d_in[21];
  const float* gnlw  = (const float*)d_in[22];
  const float* gnlb  = (const float*)d_in[23];

  const int M = in_sizes[0] / DCH;
  const int N = in_sizes[1] / DCH;
  const int E = in_sizes[4];

  float *qc, *nc, *accb, *agts1;
  unsigned char* wp;
  cudaGetSymbolAddress((void**)&qc,    g_qc);
  cudaGetSymbolAddress((void**)&nc,    g_nc);
  cudaGetSymbolAddress((void**)&accb,  g_acc);
  cudaGetSymbolAddress((void**)&agts1, g_agts);
  cudaGetSymbolAddress((void**)&wp,    g_wp);

  cudaFuncSetAttribute(mn_kernel, cudaFuncAttributeMaxDynamicSharedMemorySize, SMEM_SZ);
  cudaFuncSetAttribute(e_kernel,  cudaFuncAttributeMaxDynamicSharedMemorySize, SMEM_SZ);
  cudaFuncSetAttribute(f_kernel,  cudaFuncAttributeMaxDynamicSharedMemorySize, SMEM_SZ);

  const int mb = (M + TMR - 1) / TMR;
  const int nb = (N + TMR - 1) / TMR;
  const int eb = (E + TMR - 1) / TMR;

  wpack_kernel<<<16, 128>>>(Wq, Wc1, Wc2, Wa, Wl, Wd2, wp);

  const float* agts_in = actors;
  for (int L = 0; L < 2; L++) {
    P p = {};
    p.agts = agts_in;
    p.nodes = nodes;
    p.actor_ctrs = actor_ctrs;
    p.node_ctrs = node_ctrs;
    p.hi = hi;
    p.wi = wi;
    p.wp = wp + (size_t)L * 8 * SLAB_B;
    p.Wd1 = Wd1 + L * DCH * 2;
    p.bd1 = bd1 + L * DCH;
    p.gnq_w = gnqw + L * DCH;   p.gnq_b = gnqb + L * DCH;
    p.gnd2_w = gnd2w + L * DCH; p.gnd2_b = gnd2b + L * DCH;
    p.gnc1_w = gnc1w + L * DCH; p.gnc1_b = gnc1b + L * DCH;
    p.gnn_w = gnnw + L * DCH;   p.gnn_b = gnnb + L * DCH;
    p.gnl_w = gnlw + L * DCH;   p.gnl_b = gnlb + L * DCH;
    p.qc = qc; p.nc = nc; p.acc = accb;
    p.out = (L == 0) ? agts1 : (float*)d_out;
    p.M = M; p.N = N; p.E = E; p.mb = mb; p.nb = nb;

    mn_kernel<<<mb + nb + mb, 256, SMEM_SZ>>>(p);
    e_kernel<<<eb, 256, SMEM_SZ>>>(p);
    f_kernel<<<mb, 256, SMEM_SZ>>>(p);

    agts_in = agts1;
  }
}

// round 11
// speedup vs baseline: 3.1921x; 1.0609x over previous
#include <cuda_runtime.h>
#include <cuda_fp16.h>
#include <cstdint>

#define DCH 128
#define TMR 128
#define ROWB 272               // 256B data + 16B pad

#define OFF_A   0
#define OFF_B0  (128 * ROWB)                 // 34816
#define OFF_B1  (2 * 128 * ROWB)             // 69632
#define OFF_PS  (3 * 128 * ROWB)             // 104448 : ps[2][128], pq[2][128]
#define SMEM_SZ (OFF_PS + 2048 + 64)

#define SLAB_B  (128 * 256)                  // fp16 row-major weight plane

// ---------------- scratch (alloc-free) ----------------
__device__ float g_qc[4000 * 128];
__device__ float g_nc0[20000 * 128];
__device__ float g_nc1[20000 * 128];
__device__ float g_acc[4000 * 128];
__device__ float g_agts[4000 * 128];
__device__ __align__(16) unsigned char g_wp[2 * 8 * SLAB_B];

// slabs: 0=Wq 1=Wc1a 2=Wc1b 3=Wc1c 4=Wc2 5=Wa 6=Wl 7=Wd2

struct P {
  const float* agts;           // A source for agts-job (layer input)
  const float* nodes;
  const float* actor_ctrs; const float* node_ctrs;
  const int* hi; const int* wi;
  const unsigned char* wp;     // current layer slabs
  const unsigned char* wpPrev; // previous layer slabs (for f-recompute)
  const float* Wd1; const float* bd1;
  const float *gnq_w, *gnq_b, *gnd2_w, *gnd2_b, *gnc1_w, *gnc1_b,
              *gnn_w, *gnn_b, *gnl_w, *gnl_b;
  const float *gnn0_w, *gnn0_b, *gnl0_w, *gnl0_b;  // L0 f params (mn1 recompute)
  const float* res;            // residual source for f-recompute
  float *qc, *nc, *nc1, *acc, *agts1, *out;
  int M, N, E, mb, nb;
};

__device__ __forceinline__ uint32_t smem_u32(const void* p) {
  uint32_t a;
  asm("{ .reg .u64 t; cvta.to.shared.u64 t, %1; cvt.u32.u64 %0, t; }" : "=r"(a) : "l"(p));
  return a;
}
#define LDSM4(r0, r1, r2, r3, addr) \
  asm volatile("ldmatrix.sync.aligned.m8n8.x4.shared.b16 {%0,%1,%2,%3}, [%4];" \
    : "=r"(r0), "=r"(r1), "=r"(r2), "=r"(r3) : "r"(addr))
#define STS32(addr, v) \
  asm volatile("st.shared.u32 [%0], %1;" :: "r"(addr), "r"(v))
#define CP_A16(dst, src) \
  asm volatile("cp.async.cg.shared.global [%0], [%1], 16;" :: "r"(dst), "l"(src))
#define CP_COMMIT() asm volatile("cp.async.commit_group;" ::: "memory")
#define CP_WAIT(n)  asm volatile("cp.async.wait_group %0;" :: "n"(n) : "memory")
#define REDV2(ptr, x, y) \
  asm volatile("red.global.v2.f32.add [%0], {%1, %2};" :: "l"(ptr), "f"(x), "f"(y) : "memory")
#define PREF_L2(ptr) asm volatile("prefetch.global.L2 [%0];" :: "l"(ptr))

__device__ __forceinline__ uint32_t h2pack(float lo, float hi) {
  uint32_t r;
  asm("cvt.rn.f16x2.f32 %0, %1, %2;" : "=r"(r) : "f"(hi), "f"(lo));
  return r;
}

__device__ __forceinline__ void mma_h(float c[4], const uint32_t a[4],
                                      uint32_t b0, uint32_t b1) {
  asm volatile(
    "mma.sync.aligned.m16n8k16.row.col.f32.f16.f16.f32 "
    "{%0,%1,%2,%3}, {%4,%5,%6,%7}, {%8,%9}, {%0,%1,%2,%3};"
    : "+f"(c[0]), "+f"(c[1]), "+f"(c[2]), "+f"(c[3])
    : "r"(a[0]), "r"(a[1]), "r"(a[2]), "r"(a[3]), "r"(b0), "r"(b1));
}

__device__ __forceinline__ void store_A_h(char* smem, const float v[32], int r, int q) {
  char* rowp = smem + OFF_A + r * ROWB + q * 64;
#pragma unroll
  for (int a = 0; a < 4; a++) {
    uint4 o = make_uint4(h2pack(v[8 * a],     v[8 * a + 1]),
                         h2pack(v[8 * a + 2], v[8 * a + 3]),
                         h2pack(v[8 * a + 4], v[8 * a + 5]),
                         h2pack(v[8 * a + 6], v[8 * a + 7]));
    *(uint4*)(rowp + a * 16) = o;
  }
}

__device__ __forceinline__ void copy_B_async(char* smem, int bOff, const unsigned char* wps) {
  const uint32_t dst = smem_u32(smem) + bOff;
  for (int i = threadIdx.x; i < 2048; i += 256) {
    int row = i >> 4, u = i & 15;
    CP_A16(dst + row * ROWB + u * 16, wps + (size_t)i * 16);
  }
  CP_COMMIT();
}

__device__ __forceinline__ void mainloop_h(const char* smem, int bOff, float acc[2][8][4],
                                           int rowb, int cwb, int lane) {
  const uint32_t Ab = smem_u32(smem) + OFF_A;
  const uint32_t Bb = smem_u32(smem) + bOff;
  const uint32_t aAddr = Ab + (rowb + (lane & 15)) * ROWB + ((lane >> 4) << 4);
  const uint32_t bAddr = Bb + (cwb + ((lane >> 4) << 3) + (lane & 7)) * ROWB
                            + ((lane & 8) ? 16 : 0);
#pragma unroll
  for (int ms = 0; ms < 2; ms++)
#pragma unroll
    for (int ns = 0; ns < 8; ns++)
#pragma unroll
      for (int q = 0; q < 4; q++) acc[ms][ns][q] = 0.f;
#pragma unroll
  for (int ks = 0; ks < 8; ks++) {
    uint32_t a[2][4], b[4][4];
    LDSM4(a[0][0], a[0][1], a[0][2], a[0][3], aAddr + ks * 32);
    LDSM4(a[1][0], a[1][1], a[1][2], a[1][3], aAddr + 16 * ROWB + ks * 32);
#pragma unroll
    for (int pr = 0; pr < 4; pr++)
      LDSM4(b[pr][0], b[pr][1], b[pr][2], b[pr][3], bAddr + pr * 16 * ROWB + ks * 32);
#pragma unroll
    for (int ns = 0; ns < 8; ns++) {
      uint32_t b0 = b[ns >> 1][(ns & 1) * 2], b1 = b[ns >> 1][(ns & 1) * 2 + 1];
      mma_h(acc[0][ns], a[0], b0, b1);
      mma_h(acc[1][ns], a[1], b0, b1);
    }
  }
}

__device__ __forceinline__ void gn_ep(float f[2][8][4], char* smem,
                                      const float* gnw, const float* gnb,
                                      int rowb, int cwb, int nw, int g, int tg,
                                      bool dorelu) {
  float* ps = (float*)(smem + OFF_PS);
  float* pq = ps + 256;
#pragma unroll
  for (int ms = 0; ms < 2; ms++)
#pragma unroll
    for (int h = 0; h < 2; h++) {
      float s = 0.f, q = 0.f;
#pragma unroll
      for (int ns = 0; ns < 8; ns++)
#pragma unroll
        for (int j = 0; j < 2; j++) {
          float v = f[ms][ns][2 * h + j];
          s += v;
          q = fmaf(v, v, q);
        }
      s += __shfl_xor_sync(0xffffffffu, s, 1);
      q += __shfl_xor_sync(0xffffffffu, q, 1);
      s += __shfl_xor_sync(0xffffffffu, s, 2);
      q += __shfl_xor_sync(0xffffffffu, q, 2);
      const int r = rowb + ms * 16 + h * 8 + g;
      if (tg == 0) { ps[nw * 128 + r] = s; pq[nw * 128 + r] = q; }
    }
  __syncthreads();
  const int c0 = cwb + tg * 2;
#pragma unroll
  for (int ms = 0; ms < 2; ms++)
#pragma unroll
    for (int h = 0; h < 2; h++) {
      const int r = rowb + ms * 16 + h * 8 + g;
      float s = ps[r] + ps[128 + r];
      float q = pq[r] + pq[128 + r];
      float m = s * (1.f / DCH);
      float var = q * (1.f / DCH) - m * m;
      float inv = rsqrtf(var + 1e-5f);
#pragma unroll
      for (int ns = 0; ns < 8; ns++) {
        float2 gw = *(const float2*)(gnw + c0 + ns * 8);
        float2 gb = *(const float2*)(gnb + c0 + ns * 8);
        float a0 = fmaf((f[ms][ns][2 * h]     - m) * inv, gw.x, gb.x);
        float a1 = fmaf((f[ms][ns][2 * h + 1] - m) * inv, gw.y, gb.y);
        if (dorelu) { a0 = fmaxf(a0, 0.f); a1 = fmaxf(a1, 0.f); }
        f[ms][ns][2 * h]     = a0;
        f[ms][ns][2 * h + 1] = a1;
      }
    }
}

__device__ __forceinline__ void repack_A(const float f[2][8][4], char* smem,
                                         int rowb, int cwb, int g, int tg) {
  const uint32_t Ab = smem_u32(smem) + OFF_A;
#pragma unroll
  for (int ms = 0; ms < 2; ms++)
#pragma unroll
    for (int h = 0; h < 2; h++) {
      const int r = rowb + ms * 16 + h * 8 + g;
#pragma unroll
      for (int ns = 0; ns < 8; ns++) {
        const int c = cwb + ns * 8 + tg * 2;
        STS32(Ab + r * ROWB + c * 2, h2pack(f[ms][ns][2 * h], f[ms][ns][2 * h + 1]));
      }
    }
}

__device__ __forceinline__ void store_plain(const float f[2][8][4], float* Y, int row0,
                                            int rows, int rowb, int cwb, int g, int tg) {
  const int c0 = cwb + tg * 2;
#pragma unroll
  for (int ms = 0; ms < 2; ms++)
#pragma unroll
    for (int h = 0; h < 2; h++) {
      const int gr = row0 + rowb + ms * 16 + h * 8 + g;
      if (gr < rows) {
        float* dst = Y + (size_t)gr * DCH + c0;
#pragma unroll
        for (int ns = 0; ns < 8; ns++)
          *(float2*)(dst + ns * 8) =
              make_float2(f[ms][ns][2 * h], f[ms][ns][2 * h + 1]);
      }
    }
}

__device__ __forceinline__ void load_A_h(char* smem, const float* X, int row0, int rows) {
  const int q = threadIdx.x & 3;
  for (int r = threadIdx.x >> 2; r < TMR; r += 64) {
    const int gr = row0 + r;
    const float* px = X + (size_t)gr * DCH + q * 32;
    float v[32];
#pragma unroll
    for (int i = 0; i < 8; i++) {
      float4 t = (gr < rows) ? *(const float4*)(px + 4 * i) : make_float4(0.f, 0.f, 0.f, 0.f);
      v[4 * i] = t.x; v[4 * i + 1] = t.y; v[4 * i + 2] = t.z; v[4 * i + 3] = t.w;
    }
    store_A_h(smem, v, r, q);
  }
}

// load A = relu(gn(X)) rows (f-style input stage)
__device__ __forceinline__ void load_A_gn(char* smem, const float* X, int row0, int rows,
                                          const float* gnw, const float* gnb) {
  const int q = threadIdx.x & 3;
  for (int r = threadIdx.x >> 2; r < TMR; r += 64) {
    const int gr = row0 + r;
    float v[32];
    const float* px = X + (size_t)gr * DCH + q * 32;
#pragma unroll
    for (int i = 0; i < 8; i++) {
      float4 t = (gr < rows) ? *(const float4*)(px + 4 * i) : make_float4(0.f, 0.f, 0.f, 0.f);
      v[4 * i] = t.x; v[4 * i + 1] = t.y; v[4 * i + 2] = t.z; v[4 * i + 3] = t.w;
    }
    float s = 0.f, qq = 0.f;
#pragma unroll
    for (int i = 0; i < 32; i++) { s += v[i]; qq = fmaf(v[i], v[i], qq); }
    s  += __shfl_xor_sync(0xffffffffu, s, 1);
    qq += __shfl_xor_sync(0xffffffffu, qq, 1);
    s  += __shfl_xor_sync(0xffffffffu, s, 2);
    qq += __shfl_xor_sync(0xffffffffu, qq, 2);
    float m = s * (1.f / DCH);
    float var = qq * (1.f / DCH) - m * m;
    float inv = rsqrtf(var + 1e-5f);
#pragma unroll
    for (int i = 0; i < 32; i++) {
      const int c = q * 32 + i;
      v[i] = fmaxf(fmaf((v[i] - m) * inv, gnw[c], gnb[c]), 0.f);
    }
    store_A_h(smem, v, r, q);
  }
}

// ---------------- weight pack ----------------
__global__ void wpack_kernel(const float* Wq, const float* Wc1, const float* Wc2,
                             const float* Wa, const float* Wl, const float* Wd2,
                             unsigned char* wp) {
  int L = blockIdx.x >> 3, s = blockIdx.x & 7;
  const float* src;
  int ldw = DCH, coff = 0;
  switch (s) {
    case 0: src = Wq  + (size_t)L * DCH * DCH; break;
    case 1: src = Wc1 + (size_t)L * DCH * 3 * DCH; ldw = 3 * DCH; coff = 0;       break;
    case 2: src = Wc1 + (size_t)L * DCH * 3 * DCH; ldw = 3 * DCH; coff = DCH;     break;
    case 3: src = Wc1 + (size_t)L * DCH * 3 * DCH; ldw = 3 * DCH; coff = 2 * DCH; break;
    case 4: src = Wc2 + (size_t)L * DCH * DCH; break;
    case 5: src = Wa  + (size_t)L * DCH * DCH; break;
    case 6: src = Wl  + (size_t)L * DCH * DCH; break;
    default: src = Wd2 + (size_t)L * DCH * DCH; break;
  }
  unsigned char* dst = wp + (size_t)(L * 8 + s) * SLAB_B;
  const int j = threadIdx.x;
  const float* wr = src + (size_t)j * ldw + coff;
#pragma unroll
  for (int a = 0; a < 16; a++) {
    uint2 o = make_uint2(h2pack(wr[8 * a],     wr[8 * a + 1]),
                         h2pack(wr[8 * a + 2], wr[8 * a + 3]));
    uint2 o2 = make_uint2(h2pack(wr[8 * a + 4], wr[8 * a + 5]),
                          h2pack(wr[8 * a + 6], wr[8 * a + 7]));
    *(uint4*)(dst + (size_t)j * 256 + a * 16) = make_uint4(o.x, o.y, o2.x, o2.y);
  }
}

// ---------------- mn0: {agts-job: Wa,Wq,Wc1b | nodes-job: Wc1c(L0),Wc1c(L1)} ----------------
__global__ void __launch_bounds__(256, 2) mn0_kernel(P p) {
  extern __shared__ char smem[];
  const int tid = threadIdx.x, warp = tid >> 5, lane = tid & 31;
  const int mw = warp & 3, nw = warp >> 2;
  const int rowb = mw * 32, cwb = nw * 64, g = lane >> 2, tg = lane & 3;
  const int b = blockIdx.x;
  float f[2][8][4];

  if (b < p.mb) {
    const int row0 = b * TMR;
    copy_B_async(smem, OFF_B0, p.wp + 5 * SLAB_B);   // Wa   g0
    copy_B_async(smem, OFF_B1, p.wp + 0 * SLAB_B);   // Wq   g1
    load_A_h(smem, p.agts, row0, p.M);
    CP_WAIT(1);
    __syncthreads();
    mainloop_h(smem, OFF_B0, f, rowb, cwb, lane);
    store_plain(f, p.acc, row0, p.M, rowb, cwb, g, tg);
    __syncthreads();                                 // all done reading B0
    copy_B_async(smem, OFF_B0, p.wp + 2 * SLAB_B);   // Wc1b g2
    CP_WAIT(1);
    __syncthreads();
    mainloop_h(smem, OFF_B1, f, rowb, cwb, lane);
    gn_ep(f, smem, p.gnq_w, p.gnq_b, rowb, cwb, nw, g, tg, true);
    repack_A(f, smem, rowb, cwb, g, tg);
    CP_WAIT(0);
    __syncthreads();
    mainloop_h(smem, OFF_B0, f, rowb, cwb, lane);
    store_plain(f, p.qc, row0, p.M, rowb, cwb, g, tg);
  } else {
    const int row0 = (b - p.mb) * TMR;
    copy_B_async(smem, OFF_B0, p.wp + 3 * SLAB_B);       // Wc1c L0
    copy_B_async(smem, OFF_B1, p.wpPrev + 3 * SLAB_B);   // Wc1c L1 (wpPrev=wp1 here)
    load_A_h(smem, p.nodes, row0, p.N);
    CP_WAIT(1);
    __syncthreads();
    mainloop_h(smem, OFF_B0, f, rowb, cwb, lane);
    store_plain(f, p.nc, row0, p.N, rowb, cwb, g, tg);
    CP_WAIT(0);
    __syncthreads();
    mainloop_h(smem, OFF_B1, f, rowb, cwb, lane);
    store_plain(f, p.nc1, row0, p.N, rowb, cwb, g, tg);
  }
}

// ---------------- mn1: f-recompute(L0) -> Wa -> Wq -> Wc1b (layer 1) ----------------
__global__ void __launch_bounds__(256, 2) mn1_kernel(P p) {
  extern __shared__ char smem[];
  const int tid = threadIdx.x, warp = tid >> 5, lane = tid & 31;
  const int mw = warp & 3, nw = warp >> 2;
  const int rowb = mw * 32, cwb = nw * 64, g = lane >> 2, tg = lane & 3;
  const int row0 = blockIdx.x * TMR;
  float f[2][8][4];

  copy_B_async(smem, OFF_B0, p.wpPrev + 6 * SLAB_B);   // Wl(L0)  g0
  copy_B_async(smem, OFF_B1, p.wp + 5 * SLAB_B);       // Wa(L1)  g1
  load_A_gn(smem, p.acc, row0, p.M, p.gnn0_w, p.gnn0_b);
  CP_WAIT(1);
  __syncthreads();
  // f-stage: agts1 = relu(gn_l(A @ Wl0^T) + actors)
  mainloop_h(smem, OFF_B0, f, rowb, cwb, lane);
  gn_ep(f, smem, p.gnl0_w, p.gnl0_b, rowb, cwb, nw, g, tg, false);
  {
    const int c0 = cwb + tg * 2;
#pragma unroll
    for (int ms = 0; ms < 2; ms++)
#pragma unroll
      for (int h = 0; h < 2; h++) {
        const int gr = row0 + rowb + ms * 16 + h * 8 + g;
        if (gr < p.M) {
          const float* rp = p.res + (size_t)gr * DCH + c0;
#pragma unroll
          for (int ns = 0; ns < 8; ns++) {
            float2 rv = *(const float2*)(rp + ns * 8);
            f[ms][ns][2 * h]     = fmaxf(f[ms][ns][2 * h]     + rv.x, 0.f);
            f[ms][ns][2 * h + 1] = fmaxf(f[ms][ns][2 * h + 1] + rv.y, 0.f);
          }
        } else {
#pragma unroll
          for (int ns = 0; ns < 8; ns++) {
            f[ms][ns][2 * h] = 0.f;
            f[ms][ns][2 * h + 1] = 0.f;
          }
        }
      }
  }
  store_plain(f, p.agts1, row0, p.M, rowb, cwb, g, tg);
  copy_B_async(smem, OFF_B0, p.wp + 0 * SLAB_B);       // Wq(L1) g2 (B0 reads done at gn_ep sync)
  repack_A(f, smem, rowb, cwb, g, tg);
  CP_WAIT(1);
  __syncthreads();
  // Wa stage
  mainloop_h(smem, OFF_B1, f, rowb, cwb, lane);
  store_plain(f, p.acc, row0, p.M, rowb, cwb, g, tg);
  __syncthreads();                                     // all done reading B1
  copy_B_async(smem, OFF_B1, p.wp + 2 * SLAB_B);       // Wc1b(L1) g3
  CP_WAIT(1);
  __syncthreads();
  // Wq stage
  mainloop_h(smem, OFF_B0, f, rowb, cwb, lane);
  gn_ep(f, smem, p.gnq_w, p.gnq_b, rowb, cwb, nw, g, tg, true);
  repack_A(f, smem, rowb, cwb, g, tg);
  CP_WAIT(0);
  __syncthreads();
  // Wc1b stage
  mainloop_h(smem, OFF_B1, f, rowb, cwb, lane);
  store_plain(f, p.qc, row0, p.M, rowb, cwb, g, tg);
}

// ---------------- E kernel: fused dist-MLP -> ctx-MLP -> scatter ----------------
__global__ void __launch_bounds__(256, 2) e_kernel(P p) {
  extern __shared__ char smem[];
  const int tid = threadIdx.x, warp = tid >> 5, lane = tid & 31;
  const int mw = warp & 3, nw = warp >> 2;
  const int rowb = mw * 32, cwb = nw * 64, g = lane >> 2, tg = lane & 3;
  const int row0 = blockIdx.x * TMR;
  float f[2][8][4];

  copy_B_async(smem, OFF_B0, p.wp + 7 * SLAB_B);     // Wd2   (g0)
  copy_B_async(smem, OFF_B1, p.wp + 1 * SLAB_B);     // Wc1a  (g1)

  // stage 1 A: relu(ctr_d @ Wd1^T + bd1)  (+ L2 prefetch of gather rows)
  {
    const int q = tid & 3;
    for (int r = tid >> 2; r < TMR; r += 64) {
      const int gr = row0 + r;
      float cx = 0.f, cy = 0.f;
      if (gr < p.E) {
        int h = p.hi[gr], w = p.wi[gr];
        cx = p.actor_ctrs[2 * h]     - p.node_ctrs[2 * w];
        cy = p.actor_ctrs[2 * h + 1] - p.node_ctrs[2 * w + 1];
        PREF_L2(p.qc + (size_t)h * DCH + q * 32);
        PREF_L2(p.nc + (size_t)w * DCH + q * 32);
      }
      float v[32];
#pragma unroll
      for (int i = 0; i < 32; i++) {
        const int k = q * 32 + i;
        v[i] = fmaxf(fmaf(cx, p.Wd1[2 * k], fmaf(cy, p.Wd1[2 * k + 1], p.bd1[k])), 0.f);
      }
      store_A_h(smem, v, r, q);
    }
  }
  CP_WAIT(1);
  __syncthreads();
  mainloop_h(smem, OFF_B0, f, rowb, cwb, lane);
  gn_ep(f, smem, p.gnd2_w, p.gnd2_b, rowb, cwb, nw, g, tg, true);
  copy_B_async(smem, OFF_B0, p.wp + 4 * SLAB_B);     // Wc2  (g2)
  repack_A(f, smem, rowb, cwb, g, tg);
  CP_WAIT(1);
  __syncthreads();

  // stage 2: + qc[hi] + nc[wi], gn, relu
  mainloop_h(smem, OFF_B1, f, rowb, cwb, lane);
  {
    const int c0 = cwb + tg * 2;
#pragma unroll
    for (int ms = 0; ms < 2; ms++)
#pragma unroll
      for (int h = 0; h < 2; h++) {
        const int gr = row0 + rowb + ms * 16 + h * 8 + g;
        if (gr < p.E) {
          const float* p1 = p.qc + (size_t)p.hi[gr] * DCH + c0;
          const float* p2 = p.nc + (size_t)p.wi[gr] * DCH + c0;
#pragma unroll
          for (int ns = 0; ns < 8; ns++) {
            float2 v1 = *(const float2*)(p1 + ns * 8);
            float2 v2 = *(const float2*)(p2 + ns * 8);
            f[ms][ns][2 * h]     += v1.x + v2.x;
            f[ms][ns][2 * h + 1] += v1.y + v2.y;
          }
        }
      }
  }
  gn_ep(f, smem, p.gnc1_w, p.gnc1_b, rowb, cwb, nw, g, tg, true);
  repack_A(f, smem, rowb, cwb, g, tg);
  CP_WAIT(0);
  __syncthreads();

  // stage 3: acc[hi] += cf @ Wc2^T  (vector reductions)
  mainloop_h(smem, OFF_B0, f, rowb, cwb, lane);
  {
    const int c0 = cwb + tg * 2;
#pragma unroll
    for (int ms = 0; ms < 2; ms++)
#pragma unroll
      for (int h = 0; h < 2; h++) {
        const int gr = row0 + rowb + ms * 16 + h * 8 + g;
        if (gr < p.E) {
          float* dst = p.acc + (size_t)p.hi[gr] * DCH + c0;
#pragma unroll
          for (int ns = 0; ns < 8; ns++)
            REDV2(dst + ns * 8, f[ms][ns][2 * h], f[ms][ns][2 * h + 1]);
        }
      }
  }
}

// ---------------- F kernel (final layer only) ----------------
__global__ void __launch_bounds__(256, 2) f_kernel(P p) {
  extern __shared__ char smem[];
  const int tid = threadIdx.x, warp = tid >> 5, lane = tid & 31;
  const int mw = warp & 3, nw = warp >> 2;
  const int rowb = mw * 32, cwb = nw * 64, g = lane >> 2, tg = lane & 3;
  const int row0 = blockIdx.x * TMR;
  float f[2][8][4];

  copy_B_async(smem, OFF_B0, p.wp + 6 * SLAB_B);     // Wl
  load_A_gn(smem, p.acc, row0, p.M, p.gnn_w, p.gnn_b);
  CP_WAIT(0);
  __syncthreads();
  mainloop_h(smem, OFF_B0, f, rowb, cwb, lane);
  gn_ep(f, smem, p.gnl_w, p.gnl_b, rowb, cwb, nw, g, tg, false);
  {
    const int c0 = cwb + tg * 2;
#pragma unroll
    for (int ms = 0; ms < 2; ms++)
#pragma unroll
      for (int h = 0; h < 2; h++) {
        const int gr = row0 + rowb + ms * 16 + h * 8 + g;
        if (gr < p.M) {
          const float* rp = p.agts + (size_t)gr * DCH + c0;
          float* dst = p.out + (size_t)gr * DCH + c0;
#pragma unroll
          for (int ns = 0; ns < 8; ns++) {
            float2 rv = *(const float2*)(rp + ns * 8);
            *(float2*)(dst + ns * 8) =
                make_float2(fmaxf(f[ms][ns][2 * h]     + rv.x, 0.f),
                            fmaxf(f[ms][ns][2 * h + 1] + rv.y, 0.f));
          }
        }
      }
  }
}

extern "C" void kernel_launch(void* const* d_in, const int* in_sizes, int n_in,
                              void* d_out, int out_size) {
  const float* actors     = (const float*)d_in[0];
  const float* nodes      = (const float*)d_in[1];
  const float* actor_ctrs = (const float*)d_in[2];
  const float* node_ctrs  = (const float*)d_in[3];
  const int*   hi         = (const int*)d_in[4];
  const int*   wi         = (const int*)d_in[5];
  const float* Wd1   = (const float*)d_in[6];
  const float* bd1   = (const float*)d_in[7];
  const float* Wd2   = (const float*)d_in[8];
  const float* gnd2w = (const float*)d_in[9];
  const float* gnd2b = (const float*)d_in[10];
  const float* Wq    = (const float*)d_in[11];
  const float* gnqw  = (const float*)d_in[12];
  const float* gnqb  = (const float*)d_in[13];
  const float* Wc1   = (const float*)d_in[14];
  const float* gnc1w = (const float*)d_in[15];
  const float* gnc1b = (const float*)d_in[16];
  const float* Wc2   = (const float*)d_in[17];
  const float* Wa    = (const float*)d_in[18];
  const float* gnnw  = (const float*)d_in[19];
  const float* gnnb  = (const float*)d_in[20];
  const float* Wl    = (const float*)d_in[21];
  const float* gnlw  = (const float*)d_in[22];
  const float* gnlb  = (const float*)d_in[23];

  const int M = in_sizes[0] / DCH;
  const int N = in_sizes[1] / DCH;
  const int E = in_sizes[4];

  float *qc, *nc0, *nc1, *accb, *agts1;
  unsigned char* wp;
  cudaGetSymbolAddress((void**)&qc,    g_qc);
  cudaGetSymbolAddress((void**)&nc0,   g_nc0);
  cudaGetSymbolAddress((void**)&nc1,   g_nc1);
  cudaGetSymbolAddress((void**)&accb,  g_acc);
  cudaGetSymbolAddress((void**)&agts1, g_agts);
  cudaGetSymbolAddress((void**)&wp,    g_wp);

  cudaFuncSetAttribute(mn0_kernel, cudaFuncAttributeMaxDynamicSharedMemorySize, SMEM_SZ);
  cudaFuncSetAttribute(mn1_kernel, cudaFuncAttributeMaxDynamicSharedMemorySize, SMEM_SZ);
  cudaFuncSetAttribute(e_kernel,   cudaFuncAttributeMaxDynamicSharedMemorySize, SMEM_SZ);
  cudaFuncSetAttribute(f_kernel,   cudaFuncAttributeMaxDynamicSharedMemorySize, SMEM_SZ);

  const int mb = (M + TMR - 1) / TMR;
  const int nb = (N + TMR - 1) / TMR;
  const int eb = (E + TMR - 1) / TMR;

  wpack_kernel<<<16, 128>>>(Wq, Wc1, Wc2, Wa, Wl, Wd2, wp);

  // common param block
  P base = {};
  base.nodes = nodes;
  base.actor_ctrs = actor_ctrs;
  base.node_ctrs = node_ctrs;
  base.hi = hi; base.wi = wi;
  base.qc = qc; base.acc = accb; base.agts1 = agts1;
  base.M = M; base.N = N; base.E = E; base.mb = mb; base.nb = nb;

  const unsigned char* wp0 = wp;
  const unsigned char* wp1 = wp + (size_t)8 * SLAB_B;

  // ---- layer 0 ----
  {
    P p = base;
    p.agts = actors;
    p.wp = wp0; p.wpPrev = wp1;                 // nodes-job: B1 = Wc1c(L1)
    p.Wd1 = Wd1; p.bd1 = bd1;
    p.gnq_w = gnqw;  p.gnq_b = gnqb;
    p.gnd2_w = gnd2w; p.gnd2_b = gnd2b;
    p.gnc1_w = gnc1w; p.gnc1_b = gnc1b;
    p.nc = nc0; p.nc1 = nc1;
    mn0_kernel<<<mb + nb, 256, SMEM_SZ>>>(p);
    e_kernel<<<eb, 256, SMEM_SZ>>>(p);
  }
  // ---- layer 1 mn (with f-recompute of layer 0) ----
  {
    P p = base;
    p.wp = wp1; p.wpPrev = wp0;
    p.res = actors;                              // residual for f-recompute
    p.gnn0_w = gnnw; p.gnn0_b = gnnb;            // L0 gn_n
    p.gnl0_w = gnlw; p.gnl0_b = gnlb;            // L0 gn_l
    p.gnq_w = gnqw + DCH; p.gnq_b = gnqb + DCH;  // L1 gn_q
    mn1_kernel<<<mb, 256, SMEM_SZ>>>(p);
  }
  // ---- layer 1 e ----
  {
    P p = base;
    p.wp = wp1;
    p.Wd1 = Wd1 + DCH * 2; p.bd1 = bd1 + DCH;
    p.gnd2_w = gnd2w + DCH; p.gnd2_b = gnd2b + DCH;
    p.gnc1_w = gnc1w + DCH; p.gnc1_b = gnc1b + DCH;
    p.nc = nc1;
    e_kernel<<<eb, 256, SMEM_SZ>>>(p);
  }
  // ---- layer 1 f -> output ----
  {
    P p = base;
    p.wp = wp1;
    p.agts = agts1;                              // residual
    p.gnn_w = gnnw + DCH; p.gnn_b = gnnb + DCH;
    p.gnl_w = gnlw + DCH; p.gnl_b = gnlb + DCH;
    p.out = (float*)d_out;
    f_kernel<<<mb, 256, SMEM_SZ>>>(p);
  }
}